// round 13
// baseline (speedup 1.0000x reference)
#include <cuda_runtime.h>
#include <cuda_bf16.h>
#include <math.h>
#include <stdint.h>

#define S    2048
#define DM   1024
#define NH   16
#define DK   64
#define DFF  4096

typedef __nv_bfloat16 bf;

// ---------------- fp32 scratch ----------------------------------------------
__device__ float g_part1[S * DM];
__device__ float g_norm2[S * DM];

// ---------------- bf16 hi/lo scratch ----------------------------------------
#define DECL2(name, n) __device__ __align__(128) bf name##h[n]; __device__ __align__(128) bf name##l[n];
DECL2(g_n1,  S * DM)
DECL2(g_hv,  S * DM)
DECL2(g_q,   S * DM)
DECL2(g_k,   S * DM)
DECL2(g_v,   S * DM)
DECL2(g_vt,  S * DM)          // [NH][DK][S]
DECL2(g_ctx, S * DM)
DECL2(g_mha, S * DM)
DECL2(g_n2,  S * DM)
DECL2(g_f1,  S * DFF)
DECL2(g_p,   (size_t)NH * S * S)
// weights (K-major [N][K])
DECL2(g_wIn, DM * DM)
DECL2(g_wQ,  DM * DM)
DECL2(g_wK,  DM * DM)
DECL2(g_wV,  DM * DM)
DECL2(g_wO,  DM * DM)
DECL2(g_w2,  DM * DM)
DECL2(g_wF1, DM * DFF)
DECL2(g_wF2, DFF * DM)

// ================= helpers ===================================================
__device__ __forceinline__ uint32_t smem_u32(const void* p) {
    uint32_t a;
    asm("{ .reg .u64 t; cvta.to.shared.u64 t, %1; cvt.u32.u64 %0, t; }" : "=r"(a) : "l"(p));
    return a;
}
__device__ __forceinline__ void split2(float a, float b, uint32_t& hi, uint32_t& lo) {
    unsigned short ha = __bfloat16_as_ushort(__float2bfloat16_rn(a));
    unsigned short hb = __bfloat16_as_ushort(__float2bfloat16_rn(b));
    float fa = __bfloat162float(__ushort_as_bfloat16(ha));
    float fb = __bfloat162float(__ushort_as_bfloat16(hb));
    unsigned short la = __bfloat16_as_ushort(__float2bfloat16_rn(a - fa));
    unsigned short lb = __bfloat16_as_ushort(__float2bfloat16_rn(b - fb));
    hi = ((uint32_t)hb << 16) | ha;
    lo = ((uint32_t)lb << 16) | la;
}
__device__ __forceinline__ void split1(float a, unsigned short& h, unsigned short& l) {
    h = __bfloat16_as_ushort(__float2bfloat16_rn(a));
    l = __bfloat16_as_ushort(__float2bfloat16_rn(a - __bfloat162float(__ushort_as_bfloat16(h))));
}
__device__ __forceinline__ void ldsm_x4(uint32_t& a0, uint32_t& a1, uint32_t& a2, uint32_t& a3,
                                        uint32_t addr) {
    asm volatile("ldmatrix.sync.aligned.m8n8.x4.shared.b16 {%0,%1,%2,%3}, [%4];"
                 : "=r"(a0), "=r"(a1), "=r"(a2), "=r"(a3) : "r"(addr));
}
__device__ __forceinline__ void ldsm_x2(uint32_t& b0, uint32_t& b1, uint32_t addr) {
    asm volatile("ldmatrix.sync.aligned.m8n8.x2.shared.b16 {%0,%1}, [%2];"
                 : "=r"(b0), "=r"(b1) : "r"(addr));
}
__device__ __forceinline__ void mma16816(float* d, const uint32_t* a, const uint32_t* b) {
    asm volatile("mma.sync.aligned.m16n8k16.row.col.f32.bf16.bf16.f32 "
                 "{%0,%1,%2,%3}, {%4,%5,%6,%7}, {%8,%9}, {%0,%1,%2,%3};"
                 : "+f"(d[0]), "+f"(d[1]), "+f"(d[2]), "+f"(d[3])
                 : "r"(a[0]), "r"(a[1]), "r"(a[2]), "r"(a[3]), "r"(b[0]), "r"(b[1]));
}
__device__ __forceinline__ void cpa16(uint32_t saddr, const void* g) {
    asm volatile("cp.async.ca.shared.global [%0], [%1], 16;" :: "r"(saddr), "l"(g));
}
#define CP_COMMIT() asm volatile("cp.async.commit_group;" ::: "memory")

#define PITCH 80   // bytes per smem row (32 bf16 data + pad); ldmatrix conflict-free

// ================= pipelined HMMA GEMM body ==================================
// C[BM x BN] = alpha*(A@B) (+bias)(+res)(+relu); A/B pre-split bf16 hi/lo,
// both K-major. 2-stage cp.async pipeline, BK=32.
template<int BM, int BN, int HASBIAS, int RES, int RELU, int WF32, int WSPLIT>
__device__ __forceinline__ void mma_body(
    const bf* __restrict__ Ah, const bf* __restrict__ Al, int lda,
    const bf* __restrict__ Bh, const bf* __restrict__ Bl, int ldb,
    const float* __restrict__ bias, const float* __restrict__ Dres,
    float* __restrict__ C, bf* __restrict__ Ch, bf* __restrict__ Cl,
    int ldc, int K, float alpha)
{
    extern __shared__ __align__(128) char sm[];
    constexpr int ASZ = BM * PITCH;
    constexpr int BSZ = BN * PITCH;
    constexpr int STAGE = 2 * ASZ + 2 * BSZ;

    const int tid = threadIdx.x, lane = tid & 31, wid = tid >> 5;
    constexpr int WN  = (BN == 128) ? 4 : 2;
    constexpr int WM  = 8 / WN;
    constexpr int WTM = BM / WM;
    constexpr int WTN = BN / WN;
    constexpr int MI  = WTM / 16;
    constexpr int NI  = WTN / 8;
    const int wm = wid / WN, wn = wid % WN;
    const uint32_t sb = smem_u32(sm);

    float acc[MI][NI][4];
#pragma unroll
    for (int i = 0; i < MI; i++)
#pragma unroll
        for (int j = 0; j < NI; j++)
#pragma unroll
            for (int r = 0; r < 4; r++) acc[i][j][r] = 0.f;

    const int NC = K >> 5;

    auto issue = [&](int st, int c) {
        const uint32_t base = sb + st * STAGE;
#pragma unroll
        for (int it = 0; it < BM / 32; it++) {              // A: BM rows x4 seg x2 arr
            int idx = it * 256 + tid;
            int arr = idx / (BM * 4);
            int rem = idx % (BM * 4);
            int r = rem >> 2, sg = rem & 3;
            const bf* g = (arr ? Al : Ah) + (size_t)r * lda + (size_t)c * 32 + sg * 8;
            cpa16(base + arr * ASZ + r * PITCH + sg * 16, g);
        }
#pragma unroll
        for (int it = 0; it < BN / 32; it++) {              // B
            int idx = it * 256 + tid;
            int arr = idx / (BN * 4);
            int rem = idx % (BN * 4);
            int r = rem >> 2, sg = rem & 3;
            const bf* g = (arr ? Bl : Bh) + (size_t)r * ldb + (size_t)c * 32 + sg * 8;
            cpa16(base + 2 * ASZ + arr * BSZ + r * PITCH + sg * 16, g);
        }
    };

    issue(0, 0);
    CP_COMMIT();

    for (int c = 0; c < NC; c++) {
        const int st = c & 1;
        const bool pf = (c + 1 < NC);
        if (pf) { issue(st ^ 1, c + 1); CP_COMMIT(); }
        if (pf) { asm volatile("cp.async.wait_group 1;" ::: "memory"); }
        else    { asm volatile("cp.async.wait_group 0;" ::: "memory"); }
        __syncthreads();

        const uint32_t aH = sb + st * STAGE;
        const uint32_t aL = aH + ASZ;
        const uint32_t bH = aH + 2 * ASZ;
        const uint32_t bL = bH + BSZ;

#pragma unroll
        for (int ks = 0; ks < 2; ks++) {
            uint32_t Af[MI][4], Bhf[NI][2], Blf[NI][2];
            const int acol2 = (ks * 16 + ((lane >> 4) << 3)) * 2;
            const int bcol2 = (ks * 16 + (((lane >> 3) & 1) << 3)) * 2;
#pragma unroll
            for (int ni = 0; ni < NI; ni++) {
                uint32_t o = (uint32_t)((wn * WTN + ni * 8 + (lane & 7)) * PITCH + bcol2);
                ldsm_x2(Bhf[ni][0], Bhf[ni][1], bH + o);
                ldsm_x2(Blf[ni][0], Blf[ni][1], bL + o);
            }
#pragma unroll
            for (int mi = 0; mi < MI; mi++) {
                uint32_t o = (uint32_t)((wm * WTM + mi * 16 + (lane & 15)) * PITCH + acol2);
                ldsm_x4(Af[mi][0], Af[mi][1], Af[mi][2], Af[mi][3], aH + o);
            }
#pragma unroll
            for (int mi = 0; mi < MI; mi++)
#pragma unroll
                for (int ni = 0; ni < NI; ni++) {
                    mma16816(acc[mi][ni], Af[mi], Bhf[ni]);   // hi*hi
                    mma16816(acc[mi][ni], Af[mi], Blf[ni]);   // hi*lo
                }
#pragma unroll
            for (int mi = 0; mi < MI; mi++) {
                uint32_t o = (uint32_t)((wm * WTM + mi * 16 + (lane & 15)) * PITCH + acol2);
                ldsm_x4(Af[mi][0], Af[mi][1], Af[mi][2], Af[mi][3], aL + o);
            }
#pragma unroll
            for (int mi = 0; mi < MI; mi++)
#pragma unroll
                for (int ni = 0; ni < NI; ni++)
                    mma16816(acc[mi][ni], Af[mi], Bhf[ni]);   // lo*hi
        }
        __syncthreads();
    }

    // ---- epilogue ----
    const int groupID = lane >> 2, tig = lane & 3;
#pragma unroll
    for (int mi = 0; mi < MI; mi++) {
        const int r0 = wm * WTM + mi * 16 + groupID;
        const int r1 = r0 + 8;
#pragma unroll
        for (int ni = 0; ni < NI; ni++) {
            const int col = wn * WTN + ni * 8 + tig * 2;
            float2 v0, v1;
            v0.x = acc[mi][ni][0] * alpha; v0.y = acc[mi][ni][1] * alpha;
            v1.x = acc[mi][ni][2] * alpha; v1.y = acc[mi][ni][3] * alpha;
            if (HASBIAS) {
                v0.x += bias[col]; v0.y += bias[col + 1];
                v1.x += bias[col]; v1.y += bias[col + 1];
            }
            if (RES) {
                v0.x += Dres[(size_t)r0 * ldc + col];
                v0.y += Dres[(size_t)r0 * ldc + col + 1];
                v1.x += Dres[(size_t)r1 * ldc + col];
                v1.y += Dres[(size_t)r1 * ldc + col + 1];
            }
            if (RELU) {
                v0.x = fmaxf(v0.x, 0.f); v0.y = fmaxf(v0.y, 0.f);
                v1.x = fmaxf(v1.x, 0.f); v1.y = fmaxf(v1.y, 0.f);
            }
            if (WF32) {
                *(float2*)(C + (size_t)r0 * ldc + col) = v0;
                *(float2*)(C + (size_t)r1 * ldc + col) = v1;
            }
            if (WSPLIT) {
                uint32_t hi, lo;
                split2(v0.x, v0.y, hi, lo);
                *(uint32_t*)(Ch + (size_t)r0 * ldc + col) = hi;
                *(uint32_t*)(Cl + (size_t)r0 * ldc + col) = lo;
                split2(v1.x, v1.y, hi, lo);
                *(uint32_t*)(Ch + (size_t)r1 * ldc + col) = hi;
                *(uint32_t*)(Cl + (size_t)r1 * ldc + col) = lo;
            }
        }
    }
}

// ================= GEMM kernels ==============================================
// dense: BM=64 tiles for chip-filling grids
template<int RES, int RELU, int WF32, int WSPLIT>
__global__ void __launch_bounds__(256, 2) mm_dense_kernel(
    const bf* __restrict__ Ah, const bf* __restrict__ Al,
    const bf* __restrict__ Bh, const bf* __restrict__ Bl,
    const float* __restrict__ bias, const float* __restrict__ Dres,
    float* __restrict__ C, bf* __restrict__ Ch, bf* __restrict__ Cl,
    int N, int K)
{
    const int bm = blockIdx.y * 64, bn = blockIdx.x * 128;
    mma_body<64, 128, 1, RES, RELU, WF32, WSPLIT>(
        Ah + (size_t)bm * K, Al + (size_t)bm * K, K,
        Bh + (size_t)bn * K, Bl + (size_t)bn * K, K,
        bias + bn,
        RES ? (Dres + (size_t)bm * N + bn) : (const float*)0,
        WF32 ? (C + (size_t)bm * N + bn) : (float*)0,
        WSPLIT ? (Ch + (size_t)bm * N + bn) : (bf*)0,
        WSPLIT ? (Cl + (size_t)bm * N + bn) : (bf*)0,
        N, K, 1.0f);
}

__global__ void __launch_bounds__(256, 2) mm_qkv_kernel(
    const bf* __restrict__ Hh, const bf* __restrict__ Hl,
    const bf* __restrict__ WQh, const bf* __restrict__ WQl, const float* __restrict__ bq,
    bf* __restrict__ Qh, bf* __restrict__ Ql,
    const bf* __restrict__ WKh, const bf* __restrict__ WKl, const float* __restrict__ bk,
    bf* __restrict__ Kh, bf* __restrict__ Kl,
    const bf* __restrict__ WVh, const bf* __restrict__ WVl, const float* __restrict__ bv,
    bf* __restrict__ Vh, bf* __restrict__ Vl)
{
    const bf *Wh, *Wl; const float* b; bf *Oh, *Ol;
    if (blockIdx.z == 0)      { Wh = WQh; Wl = WQl; b = bq; Oh = Qh; Ol = Ql; }
    else if (blockIdx.z == 1) { Wh = WKh; Wl = WKl; b = bk; Oh = Kh; Ol = Kl; }
    else                      { Wh = WVh; Wl = WVl; b = bv; Oh = Vh; Ol = Vl; }
    const int bm = blockIdx.y * 64, bn = blockIdx.x * 128;
    mma_body<64, 128, 1, 0, 0, 0, 1>(
        Hh + (size_t)bm * DM, Hl + (size_t)bm * DM, DM,
        Wh + (size_t)bn * DM, Wl + (size_t)bn * DM, DM,
        b + bn, (const float*)0,
        (float*)0,
        Oh + (size_t)bm * DM + bn, Ol + (size_t)bm * DM + bn,
        DM, DM, 1.0f);
}

__global__ void __launch_bounds__(256, 2) mm_scores_kernel(
    const bf* __restrict__ Qh, const bf* __restrict__ Ql,
    const bf* __restrict__ Kh, const bf* __restrict__ Kl,
    float* __restrict__ P)
{
    const int kt = blockIdx.x, qt = blockIdx.y, h = blockIdx.z;
    if (kt > qt) return;
    mma_body<128, 128, 0, 0, 0, 1, 0>(
        Qh + (size_t)(qt * 128) * DM + h * DK, Ql + (size_t)(qt * 128) * DM + h * DK, DM,
        Kh + (size_t)(kt * 128) * DM + h * DK, Kl + (size_t)(kt * 128) * DM + h * DK, DM,
        (const float*)0, (const float*)0,
        P + (size_t)h * S * S + (size_t)(qt * 128) * S + kt * 128,
        (bf*)0, (bf*)0, S, DK, 0.125f);
}

__global__ void __launch_bounds__(256, 2) mm_ctx_kernel(
    const bf* __restrict__ Ph, const bf* __restrict__ Pl,
    const bf* __restrict__ Vth, const bf* __restrict__ Vtl,
    bf* __restrict__ Ch, bf* __restrict__ Cl)
{
    const int qt = blockIdx.x, h = blockIdx.y;
    mma_body<128, 64, 0, 0, 0, 0, 1>(
        Ph + (size_t)h * S * S + (size_t)(qt * 128) * S,
        Pl + (size_t)h * S * S + (size_t)(qt * 128) * S, S,
        Vth + (size_t)h * DK * S, Vtl + (size_t)h * DK * S, S,
        (const float*)0, (const float*)0,
        (float*)0,
        Ch + (size_t)(qt * 128) * DM + h * DK, Cl + (size_t)(qt * 128) * DM + h * DK,
        DM, (qt + 1) * 128, 1.0f);
}

// ================= fused weight prep =========================================
// All 8 weights in one launch. W[K][N] fp32 -> [N][K] bf16 hi/lo.
__global__ void __launch_bounds__(256) prep_all_kernel(
    const float* __restrict__ W_in, bf* __restrict__ wInh, bf* __restrict__ wInl,
    const float* __restrict__ Wq,  bf* __restrict__ wQh,  bf* __restrict__ wQl,
    const float* __restrict__ Wk,  bf* __restrict__ wKh,  bf* __restrict__ wKl,
    const float* __restrict__ Wv,  bf* __restrict__ wVh,  bf* __restrict__ wVl,
    const float* __restrict__ Wo,  bf* __restrict__ wOh,  bf* __restrict__ wOl,
    const float* __restrict__ W2,  bf* __restrict__ w2h,  bf* __restrict__ w2l,
    const float* __restrict__ Wf1, bf* __restrict__ wF1h, bf* __restrict__ wF1l,
    const float* __restrict__ Wf2, bf* __restrict__ wF2h, bf* __restrict__ wF2l)
{
    const int b = blockIdx.x;
    const float* W; bf* Bh; bf* Bl; int N, K, t;
    if (b < 6144) {
        const int wi = b >> 10;
        t = b & 1023;
        N = DM; K = DM;
        switch (wi) {
            case 0: W = W_in; Bh = wInh; Bl = wInl; break;
            case 1: W = Wq;   Bh = wQh;  Bl = wQl;  break;
            case 2: W = Wk;   Bh = wKh;  Bl = wKl;  break;
            case 3: W = Wv;   Bh = wVh;  Bl = wVl;  break;
            case 4: W = Wo;   Bh = wOh;  Bl = wOl;  break;
            default: W = W2;  Bh = w2h;  Bl = w2l;  break;
        }
    } else if (b < 10240) {
        t = b - 6144; N = DFF; K = DM;  W = Wf1; Bh = wF1h; Bl = wF1l;
    } else {
        t = b - 10240; N = DM; K = DFF; W = Wf2; Bh = wF2h; Bl = wF2l;
    }
    const int nx = N / 32;
    const int n0 = (t % nx) * 32, k0 = (t / nx) * 32;

    __shared__ float tt[32][33];
    const int tx = threadIdx.x & 31, ty = threadIdx.x >> 5;
#pragma unroll
    for (int i = 0; i < 4; i++) {
        int k = ty + i * 8;
        tt[k][tx] = W[(size_t)(k0 + k) * N + n0 + tx];
    }
    __syncthreads();
#pragma unroll
    for (int i = 0; i < 4; i++) {
        int n = ty + i * 8;
        float v = tt[tx][n];
        unsigned short h, l;
        split1(v, h, l);
        size_t o = (size_t)(n0 + n) * K + k0 + tx;
        Bh[o] = __ushort_as_bfloat16(h);
        Bl[o] = __ushort_as_bfloat16(l);
    }
}

// vt[h][c][s] = v[s][h*64+c]
__global__ void __launch_bounds__(256) prep_vt_kernel(
    const bf* __restrict__ Vh, const bf* __restrict__ Vl,
    bf* __restrict__ Vth, bf* __restrict__ Vtl)
{
    __shared__ bf th[32][33], tl[32][33];
    const int s0 = blockIdx.x * 32, c0 = blockIdx.y * 32, h = blockIdx.z;
    const int tx = threadIdx.x & 31, ty = threadIdx.x >> 5;
#pragma unroll
    for (int i = 0; i < 4; i++) {
        int s = ty + i * 8;
        th[s][tx] = Vh[(size_t)(s0 + s) * DM + h * DK + c0 + tx];
        tl[s][tx] = Vl[(size_t)(s0 + s) * DM + h * DK + c0 + tx];
    }
    __syncthreads();
#pragma unroll
    for (int i = 0; i < 4; i++) {
        int cc = ty + i * 8;
        size_t o = ((size_t)h * DK + c0 + cc) * S + s0 + tx;
        Vth[o] = th[tx][cc];
        Vtl[o] = tl[tx][cc];
    }
}

// ================= LN / softmax ==============================================
__device__ __forceinline__ float warp_sum(float v) {
#pragma unroll
    for (int o = 16; o > 0; o >>= 1) v += __shfl_xor_sync(0xffffffffu, v, o);
    return v;
}
__device__ __forceinline__ float warp_max(float v) {
#pragma unroll
    for (int o = 16; o > 0; o >>= 1) v = fmaxf(v, __shfl_xor_sync(0xffffffffu, v, o));
    return v;
}
__device__ __forceinline__ float block_sum(float v, float* red) {
    const int tid = threadIdx.x;
    v = warp_sum(v);
    if ((tid & 31) == 0) red[tid >> 5] = v;
    __syncthreads();
    float r = (tid < 8) ? red[tid] : 0.f;
    r = warp_sum(r);
    if (tid == 0) red[0] = r;
    __syncthreads();
    return red[0];
}
__device__ __forceinline__ float block_max(float v, float* red) {
    const int tid = threadIdx.x;
    v = warp_max(v);
    if ((tid & 31) == 0) red[tid >> 5] = v;
    __syncthreads();
    float r = (tid < 8) ? red[tid] : -3.0e38f;
    r = warp_max(r);
    if (tid == 0) red[0] = r;
    __syncthreads();
    return red[0];
}

template<int WF32>
__global__ void __launch_bounds__(256) ln_kernel(
    const float* __restrict__ x, const float* __restrict__ g, const float* __restrict__ b,
    float* __restrict__ y, bf* __restrict__ yh, bf* __restrict__ yl)
{
    const int row = blockIdx.x;
    const float4* xr = (const float4*)(x + (size_t)row * DM);
    __shared__ float red[8];
    const int tid = threadIdx.x;

    float4 xv = xr[tid];
    float s = xv.x + xv.y + xv.z + xv.w;
    const float mean = block_sum(s, red) * (1.f / DM);
    __syncthreads();

    float dx = xv.x - mean, dy = xv.y - mean, dz = xv.z - mean, dw = xv.w - mean;
    float v = dx * dx + dy * dy + dz * dz + dw * dw;
    const float var = block_sum(v, red) * (1.f / DM);
    const float inv = 1.f / (sqrtf(var) + 1e-6f);

    float4 gv = ((const float4*)g)[tid];
    float4 bv = ((const float4*)b)[tid];
    float4 o;
    o.x = gv.x * (dx * inv) + bv.x;
    o.y = gv.y * (dy * inv) + bv.y;
    o.z = gv.z * (dz * inv) + bv.z;
    o.w = gv.w * (dw * inv) + bv.w;
    if (WF32) ((float4*)(y + (size_t)row * DM))[tid] = o;

    uint32_t h0, l0, h1, l1;
    split2(o.x, o.y, h0, l0);
    split2(o.z, o.w, h1, l1);
    *(uint2*)(yh + (size_t)row * DM + tid * 4) = make_uint2(h0, h1);
    *(uint2*)(yl + (size_t)row * DM + tid * 4) = make_uint2(l0, l1);
}

__global__ void __launch_bounds__(256) softmax_kernel(
    float* __restrict__ P, bf* __restrict__ Ph, bf* __restrict__ Pl)
{
    const int row = blockIdx.x;          // h*S + q
    const int qi = row & (S - 1);
    float* p = P + (size_t)row * S;
    bf* ph = Ph + (size_t)row * S;
    bf* pl = Pl + (size_t)row * S;
    const int n = qi + 1;
    __shared__ float red[8];
    const int tid = threadIdx.x;

    float m = -3.0e38f;
    for (int j = tid; j < n; j += 256) m = fmaxf(m, p[j]);
    m = block_max(m, red);
    __syncthreads();

    float sum = 0.f;
    for (int j = tid; j < n; j += 256) { float e = expf(p[j] - m); p[j] = e; sum += e; }
    sum = block_sum(sum, red);
    const float inv = 1.f / sum;

    for (int j = tid; j < n; j += 256) {
        float val = p[j] * inv;
        p[j] = val;
        unsigned short h, l;
        split1(val, h, l);
        ph[j] = __ushort_as_bfloat16(h);
        pl[j] = __ushort_as_bfloat16(l);
    }
    const bf z = __ushort_as_bfloat16(0);
    for (int j = n + tid; j < S; j += 256) { p[j] = 0.f; ph[j] = z; pl[j] = z; }
}

// ================= host orchestration ========================================
#define GETP(var, sym) cudaGetSymbolAddress((void**)&var, sym)

extern "C" void kernel_launch(void* const* d_in, const int* in_sizes, int n_in,
                              void* d_out, int out_size)
{
    const float* x     = (const float*)d_in[0];
    const float* g1    = (const float*)d_in[1];
    const float* beta1 = (const float*)d_in[2];
    const float* W_in  = (const float*)d_in[3];
    const float* b_in  = (const float*)d_in[4];
    const float* Wq    = (const float*)d_in[5];
    const float* bq    = (const float*)d_in[6];
    const float* Wk    = (const float*)d_in[7];
    const float* bk    = (const float*)d_in[8];
    const float* Wv    = (const float*)d_in[9];
    const float* bv    = (const float*)d_in[10];
    const float* Wo    = (const float*)d_in[11];
    const float* bo    = (const float*)d_in[12];
    const float* W2    = (const float*)d_in[13];
    const float* b2    = (const float*)d_in[14];
    const float* g2    = (const float*)d_in[15];
    const float* beta2 = (const float*)d_in[16];
    const float* Wf1   = (const float*)d_in[17];
    const float* bf1   = (const float*)d_in[18];
    const float* Wf2   = (const float*)d_in[19];
    const float* bf2   = (const float*)d_in[20];

    float* out  = (float*)d_out;                       // [S, DM]
    float* attn = (float*)d_out + (size_t)S * DM;      // [NH, S, S]

    float *p_part1, *p_norm2;
    GETP(p_part1, g_part1); GETP(p_norm2, g_norm2);

    bf *n1h, *n1l, *hh, *hl, *qh, *ql, *kh, *kl, *vh, *vl, *vth, *vtl;
    bf *ctxh, *ctxl, *mhah, *mhal, *n2h, *n2l, *f1h, *f1l, *pph, *ppl;
    GETP(n1h, g_n1h); GETP(n1l, g_n1l);
    GETP(hh, g_hvh);  GETP(hl, g_hvl);
    GETP(qh, g_qh);   GETP(ql, g_ql);
    GETP(kh, g_kh);   GETP(kl, g_kl);
    GETP(vh, g_vh);   GETP(vl, g_vl);
    GETP(vth, g_vth); GETP(vtl, g_vtl);
    GETP(ctxh, g_ctxh); GETP(ctxl, g_ctxl);
    GETP(mhah, g_mhah); GETP(mhal, g_mhal);
    GETP(n2h, g_n2h); GETP(n2l, g_n2l);
    GETP(f1h, g_f1h); GETP(f1l, g_f1l);
    GETP(pph, g_ph);  GETP(ppl, g_pl);

    bf *wInh, *wInl, *wQh, *wQl, *wKh, *wKl, *wVh, *wVl, *wOh, *wOl, *w2h, *w2l;
    bf *wF1h, *wF1l, *wF2h, *wF2l;
    GETP(wInh, g_wInh); GETP(wInl, g_wInl);
    GETP(wQh, g_wQh);   GETP(wQl, g_wQl);
    GETP(wKh, g_wKh);   GETP(wKl, g_wKl);
    GETP(wVh, g_wVh);   GETP(wVl, g_wVl);
    GETP(wOh, g_wOh);   GETP(wOl, g_wOl);
    GETP(w2h, g_w2h);   GETP(w2l, g_w2l);
    GETP(wF1h, g_wF1h); GETP(wF1l, g_wF1l);
    GETP(wF2h, g_wF2h); GETP(wF2l, g_wF2l);

    // smem sizes per tile shape
    const int SM_D  = 2 * (2 * 64 * PITCH + 2 * 128 * PITCH);    // dense  61440
    const int SM_S  = 2 * (2 * 128 * PITCH + 2 * 128 * PITCH);   // scores 81920
    const int SM_C  = 2 * (2 * 128 * PITCH + 2 * 64 * PITCH);    // ctx    61440
    cudaFuncSetAttribute(mm_dense_kernel<0,0,0,1>, cudaFuncAttributeMaxDynamicSharedMemorySize, SM_D);
    cudaFuncSetAttribute(mm_dense_kernel<1,0,1,0>, cudaFuncAttributeMaxDynamicSharedMemorySize, SM_D);
    cudaFuncSetAttribute(mm_dense_kernel<0,1,0,1>, cudaFuncAttributeMaxDynamicSharedMemorySize, SM_D);
    cudaFuncSetAttribute(mm_qkv_kernel,    cudaFuncAttributeMaxDynamicSharedMemorySize, SM_D);
    cudaFuncSetAttribute(mm_scores_kernel, cudaFuncAttributeMaxDynamicSharedMemorySize, SM_S);
    cudaFuncSetAttribute(mm_ctx_kernel,    cudaFuncAttributeMaxDynamicSharedMemorySize, SM_C);

    // 0. all weight prep in one launch
    prep_all_kernel<<<14336, 256>>>(
        W_in, wInh, wInl, Wq, wQh, wQl, Wk, wKh, wKl, Wv, wVh, wVl,
        Wo, wOh, wOl, W2, w2h, w2l, Wf1, wF1h, wF1l, Wf2, wF2h, wF2l);

    // 1. LN1 -> hi/lo only
    ln_kernel<0><<<S, 256>>>(x, g1, beta1, nullptr, n1h, n1l);

    // 2. h = norm1 @ W_in + b_in  (hi/lo only)
    mm_dense_kernel<0,0,0,1><<<dim3(DM/128, S/64), 256, SM_D>>>(
        n1h, n1l, wInh, wInl, b_in, nullptr, nullptr, hh, hl, DM, DM);

    // 3. q/k/v
    mm_qkv_kernel<<<dim3(DM/128, S/64, 3), 256, SM_D>>>(
        hh, hl, wQh, wQl, bq, qh, ql, wKh, wKl, bk, kh, kl, wVh, wVl, bv, vh, vl);

    // 3b. V transpose per head
    prep_vt_kernel<<<dim3(S/32, DK/32, NH), 256>>>(vh, vl, vth, vtl);

    // 4. scores -> attn fp32; 5. softmax -> attn fp32 + P hi/lo
    mm_scores_kernel<<<dim3(S/128, S/128, NH), 256, SM_S>>>(qh, ql, kh, kl, attn);
    softmax_kernel<<<NH * S, 256>>>(attn, pph, ppl);

    // 6. ctx = P @ V (hi/lo only)
    mm_ctx_kernel<<<dim3(S/128, NH), 256, SM_C>>>(pph, ppl, vth, vtl, ctxh, ctxl);

    // 7. mha = ctx @ Wo + bo (hi/lo only)
    mm_dense_kernel<0,0,0,1><<<dim3(DM/128, S/64), 256, SM_D>>>(
        ctxh, ctxl, wOh, wOl, bo, nullptr, nullptr, mhah, mhal, DM, DM);

    // 8. part1 = x + mha @ W2 + b2 (fp32)
    mm_dense_kernel<1,0,1,0><<<dim3(DM/128, S/64), 256, SM_D>>>(
        mhah, mhal, w2h, w2l, b2, x, p_part1, nullptr, nullptr, DM, DM);

    // 9. LN2 -> fp32 + hi/lo
    ln_kernel<1><<<S, 256>>>(p_part1, g2, beta2, p_norm2, n2h, n2l);

    // 10. ff1 = relu(norm2 @ Wf1 + bf1) (hi/lo only)
    mm_dense_kernel<0,1,0,1><<<dim3(DFF/128, S/64), 256, SM_D>>>(
        n2h, n2l, wF1h, wF1l, bf1, nullptr, nullptr, f1h, f1l, DFF, DM);

    // 11. out = norm2 + ff1 @ Wf2 + bf2 (fp32)
    mm_dense_kernel<1,0,1,0><<<dim3(DM/128, S/64), 256, SM_D>>>(
        f1h, f1l, wF2h, wF2l, bf2, p_norm2, out, nullptr, nullptr, DM, DFF);
}

// round 14
// speedup vs baseline: 1.0505x; 1.0505x over previous
#include <cuda_runtime.h>
#include <cuda_bf16.h>
#include <math.h>
#include <stdint.h>

#define S    2048
#define DM   1024
#define NH   16
#define DK   64
#define DFF  4096

typedef __nv_bfloat16 bf;

// ---------------- fp32 scratch ----------------------------------------------
__device__ float g_part1[S * DM];
__device__ float g_norm2[S * DM];

// ---------------- bf16 hi/lo scratch ----------------------------------------
#define DECL2(name, n) __device__ __align__(128) bf name##h[n]; __device__ __align__(128) bf name##l[n];
DECL2(g_n1,  S * DM)
DECL2(g_hv,  S * DM)
DECL2(g_q,   S * DM)
DECL2(g_k,   S * DM)
DECL2(g_v,   S * DM)
DECL2(g_vt,  S * DM)          // [NH][DK][S]
DECL2(g_ctx, S * DM)
DECL2(g_mha, S * DM)
DECL2(g_n2,  S * DM)
DECL2(g_f1,  S * DFF)
DECL2(g_p,   (size_t)NH * S * S)
// weights (K-major [N][K])
DECL2(g_wIn, DM * DM)
DECL2(g_wQ,  DM * DM)
DECL2(g_wK,  DM * DM)
DECL2(g_wV,  DM * DM)
DECL2(g_wO,  DM * DM)
DECL2(g_w2,  DM * DM)
DECL2(g_wF1, DM * DFF)
DECL2(g_wF2, DFF * DM)

// ================= helpers ===================================================
__device__ __forceinline__ uint32_t smem_u32(const void* p) {
    uint32_t a;
    asm("{ .reg .u64 t; cvta.to.shared.u64 t, %1; cvt.u32.u64 %0, t; }" : "=r"(a) : "l"(p));
    return a;
}
__device__ __forceinline__ void split2(float a, float b, uint32_t& hi, uint32_t& lo) {
    unsigned short ha = __bfloat16_as_ushort(__float2bfloat16_rn(a));
    unsigned short hb = __bfloat16_as_ushort(__float2bfloat16_rn(b));
    float fa = __bfloat162float(__ushort_as_bfloat16(ha));
    float fb = __bfloat162float(__ushort_as_bfloat16(hb));
    unsigned short la = __bfloat16_as_ushort(__float2bfloat16_rn(a - fa));
    unsigned short lb = __bfloat16_as_ushort(__float2bfloat16_rn(b - fb));
    hi = ((uint32_t)hb << 16) | ha;
    lo = ((uint32_t)lb << 16) | la;
}
__device__ __forceinline__ void split1(float a, unsigned short& h, unsigned short& l) {
    h = __bfloat16_as_ushort(__float2bfloat16_rn(a));
    l = __bfloat16_as_ushort(__float2bfloat16_rn(a - __bfloat162float(__ushort_as_bfloat16(h))));
}
__device__ __forceinline__ void ldsm_x4(uint32_t& a0, uint32_t& a1, uint32_t& a2, uint32_t& a3,
                                        uint32_t addr) {
    asm volatile("ldmatrix.sync.aligned.m8n8.x4.shared.b16 {%0,%1,%2,%3}, [%4];"
                 : "=r"(a0), "=r"(a1), "=r"(a2), "=r"(a3) : "r"(addr));
}
__device__ __forceinline__ void mma16816(float* d, const uint32_t* a, const uint32_t* b) {
    asm volatile("mma.sync.aligned.m16n8k16.row.col.f32.bf16.bf16.f32 "
                 "{%0,%1,%2,%3}, {%4,%5,%6,%7}, {%8,%9}, {%0,%1,%2,%3};"
                 : "+f"(d[0]), "+f"(d[1]), "+f"(d[2]), "+f"(d[3])
                 : "r"(a[0]), "r"(a[1]), "r"(a[2]), "r"(a[3]), "r"(b[0]), "r"(b[1]));
}
__device__ __forceinline__ void cpa16(uint32_t saddr, const void* g) {
    asm volatile("cp.async.ca.shared.global [%0], [%1], 16;" :: "r"(saddr), "l"(g));
}
#define CP_COMMIT() asm volatile("cp.async.commit_group;" ::: "memory")

#define PITCH 80   // bytes per smem row (32 bf16 data + pad); ldmatrix conflict-free

// ================= pipelined HMMA GEMM body ==================================
// C[BM x BN] = alpha*(A@B) (+bias)(+res)(+relu); A/B pre-split bf16 hi/lo,
// both K-major. 2-stage cp.async pipeline, BK=32.
// B hi/lo fragments fetched with ONE merged ldmatrix.x4 per (ks,ni):
// lanes 0-15 address sBh (k0,k8), lanes 16-31 address sBl -> regs {bh0,bh1,bl0,bl1}.
template<int BM, int BN, int HASBIAS, int RES, int RELU, int WF32, int WSPLIT>
__device__ __forceinline__ void mma_body(
    const bf* __restrict__ Ah, const bf* __restrict__ Al, int lda,
    const bf* __restrict__ Bh, const bf* __restrict__ Bl, int ldb,
    const float* __restrict__ bias, const float* __restrict__ Dres,
    float* __restrict__ C, bf* __restrict__ Ch, bf* __restrict__ Cl,
    int ldc, int K, float alpha)
{
    extern __shared__ __align__(128) char sm[];
    constexpr int ASZ = BM * PITCH;
    constexpr int BSZ = BN * PITCH;
    constexpr int STAGE = 2 * ASZ + 2 * BSZ;

    const int tid = threadIdx.x, lane = tid & 31, wid = tid >> 5;
    constexpr int WN  = (BN == 128) ? 4 : 2;
    constexpr int WM  = 8 / WN;
    constexpr int WTM = BM / WM;
    constexpr int WTN = BN / WN;
    constexpr int MI  = WTM / 16;
    constexpr int NI  = WTN / 8;
    const int wm = wid / WN, wn = wid % WN;
    const uint32_t sb = smem_u32(sm);

    float acc[MI][NI][4];
#pragma unroll
    for (int i = 0; i < MI; i++)
#pragma unroll
        for (int j = 0; j < NI; j++)
#pragma unroll
            for (int r = 0; r < 4; r++) acc[i][j][r] = 0.f;

    const int NC = K >> 5;

    auto issue = [&](int st, int c) {
        const uint32_t base = sb + st * STAGE;
#pragma unroll
        for (int it = 0; it < BM / 32; it++) {              // A: BM rows x4 seg x2 arr
            int idx = it * 256 + tid;
            int arr = idx / (BM * 4);
            int rem = idx % (BM * 4);
            int r = rem >> 2, sg = rem & 3;
            const bf* g = (arr ? Al : Ah) + (size_t)r * lda + (size_t)c * 32 + sg * 8;
            cpa16(base + arr * ASZ + r * PITCH + sg * 16, g);
        }
#pragma unroll
        for (int it = 0; it < BN / 32; it++) {              // B
            int idx = it * 256 + tid;
            int arr = idx / (BN * 4);
            int rem = idx % (BN * 4);
            int r = rem >> 2, sg = rem & 3;
            const bf* g = (arr ? Bl : Bh) + (size_t)r * ldb + (size_t)c * 32 + sg * 8;
            cpa16(base + 2 * ASZ + arr * BSZ + r * PITCH + sg * 16, g);
        }
    };

    issue(0, 0);
    CP_COMMIT();

    for (int c = 0; c < NC; c++) {
        const int st = c & 1;
        const bool pf = (c + 1 < NC);
        if (pf) { issue(st ^ 1, c + 1); CP_COMMIT(); }
        if (pf) { asm volatile("cp.async.wait_group 1;" ::: "memory"); }
        else    { asm volatile("cp.async.wait_group 0;" ::: "memory"); }
        __syncthreads();

        const uint32_t aH = sb + st * STAGE;
        const uint32_t aL = aH + ASZ;
        const uint32_t bH = aH + 2 * ASZ;

#pragma unroll
        for (int ks = 0; ks < 2; ks++) {
            uint32_t Af[MI][4], Bf[NI][4];
            const int acol2 = (ks * 16 + ((lane >> 4) << 3)) * 2;
            // B merged hi/lo x4: lanes 0-7 hi@k0, 8-15 hi@k8, 16-23 lo@k0, 24-31 lo@k8
            const int bcol2 = (ks * 16 + (((lane >> 3) & 1) << 3)) * 2;
            const uint32_t bsel = (uint32_t)(lane >> 4) * BSZ;
#pragma unroll
            for (int ni = 0; ni < NI; ni++) {
                uint32_t o = (uint32_t)((wn * WTN + ni * 8 + (lane & 7)) * PITCH + bcol2) + bsel;
                ldsm_x4(Bf[ni][0], Bf[ni][1], Bf[ni][2], Bf[ni][3], bH + o);
            }
#pragma unroll
            for (int mi = 0; mi < MI; mi++) {
                uint32_t o = (uint32_t)((wm * WTM + mi * 16 + (lane & 15)) * PITCH + acol2);
                ldsm_x4(Af[mi][0], Af[mi][1], Af[mi][2], Af[mi][3], aH + o);
            }
#pragma unroll
            for (int mi = 0; mi < MI; mi++)
#pragma unroll
                for (int ni = 0; ni < NI; ni++) {
                    mma16816(acc[mi][ni], Af[mi], &Bf[ni][0]);   // hi*hi
                    mma16816(acc[mi][ni], Af[mi], &Bf[ni][2]);   // hi*lo
                }
#pragma unroll
            for (int mi = 0; mi < MI; mi++) {
                uint32_t o = (uint32_t)((wm * WTM + mi * 16 + (lane & 15)) * PITCH + acol2);
                ldsm_x4(Af[mi][0], Af[mi][1], Af[mi][2], Af[mi][3], aL + o);
            }
#pragma unroll
            for (int mi = 0; mi < MI; mi++)
#pragma unroll
                for (int ni = 0; ni < NI; ni++)
                    mma16816(acc[mi][ni], Af[mi], &Bf[ni][0]);   // lo*hi
        }
        __syncthreads();
    }

    // ---- epilogue ----
    const int groupID = lane >> 2, tig = lane & 3;
#pragma unroll
    for (int mi = 0; mi < MI; mi++) {
        const int r0 = wm * WTM + mi * 16 + groupID;
        const int r1 = r0 + 8;
#pragma unroll
        for (int ni = 0; ni < NI; ni++) {
            const int col = wn * WTN + ni * 8 + tig * 2;
            float2 v0, v1;
            v0.x = acc[mi][ni][0] * alpha; v0.y = acc[mi][ni][1] * alpha;
            v1.x = acc[mi][ni][2] * alpha; v1.y = acc[mi][ni][3] * alpha;
            if (HASBIAS) {
                v0.x += bias[col]; v0.y += bias[col + 1];
                v1.x += bias[col]; v1.y += bias[col + 1];
            }
            if (RES) {
                v0.x += Dres[(size_t)r0 * ldc + col];
                v0.y += Dres[(size_t)r0 * ldc + col + 1];
                v1.x += Dres[(size_t)r1 * ldc + col];
                v1.y += Dres[(size_t)r1 * ldc + col + 1];
            }
            if (RELU) {
                v0.x = fmaxf(v0.x, 0.f); v0.y = fmaxf(v0.y, 0.f);
                v1.x = fmaxf(v1.x, 0.f); v1.y = fmaxf(v1.y, 0.f);
            }
            if (WF32) {
                *(float2*)(C + (size_t)r0 * ldc + col) = v0;
                *(float2*)(C + (size_t)r1 * ldc + col) = v1;
            }
            if (WSPLIT) {
                uint32_t hi, lo;
                split2(v0.x, v0.y, hi, lo);
                *(uint32_t*)(Ch + (size_t)r0 * ldc + col) = hi;
                *(uint32_t*)(Cl + (size_t)r0 * ldc + col) = lo;
                split2(v1.x, v1.y, hi, lo);
                *(uint32_t*)(Ch + (size_t)r1 * ldc + col) = hi;
                *(uint32_t*)(Cl + (size_t)r1 * ldc + col) = lo;
            }
        }
    }
}

// ================= GEMM kernels (BM=128 everywhere) ==========================
template<int RES, int RELU, int WF32, int WSPLIT>
__global__ void __launch_bounds__(256, 2) mm_dense_kernel(
    const bf* __restrict__ Ah, const bf* __restrict__ Al,
    const bf* __restrict__ Bh, const bf* __restrict__ Bl,
    const float* __restrict__ bias, const float* __restrict__ Dres,
    float* __restrict__ C, bf* __restrict__ Ch, bf* __restrict__ Cl,
    int N, int K)
{
    const int bm = blockIdx.y * 128, bn = blockIdx.x * 128;
    mma_body<128, 128, 1, RES, RELU, WF32, WSPLIT>(
        Ah + (size_t)bm * K, Al + (size_t)bm * K, K,
        Bh + (size_t)bn * K, Bl + (size_t)bn * K, K,
        bias + bn,
        RES ? (Dres + (size_t)bm * N + bn) : (const float*)0,
        WF32 ? (C + (size_t)bm * N + bn) : (float*)0,
        WSPLIT ? (Ch + (size_t)bm * N + bn) : (bf*)0,
        WSPLIT ? (Cl + (size_t)bm * N + bn) : (bf*)0,
        N, K, 1.0f);
}

__global__ void __launch_bounds__(256, 2) mm_qkv_kernel(
    const bf* __restrict__ Hh, const bf* __restrict__ Hl,
    const bf* __restrict__ WQh, const bf* __restrict__ WQl, const float* __restrict__ bq,
    bf* __restrict__ Qh, bf* __restrict__ Ql,
    const bf* __restrict__ WKh, const bf* __restrict__ WKl, const float* __restrict__ bk,
    bf* __restrict__ Kh, bf* __restrict__ Kl,
    const bf* __restrict__ WVh, const bf* __restrict__ WVl, const float* __restrict__ bv,
    bf* __restrict__ Vh, bf* __restrict__ Vl)
{
    const bf *Wh, *Wl; const float* b; bf *Oh, *Ol;
    if (blockIdx.z == 0)      { Wh = WQh; Wl = WQl; b = bq; Oh = Qh; Ol = Ql; }
    else if (blockIdx.z == 1) { Wh = WKh; Wl = WKl; b = bk; Oh = Kh; Ol = Kl; }
    else                      { Wh = WVh; Wl = WVl; b = bv; Oh = Vh; Ol = Vl; }
    const int bm = blockIdx.y * 128, bn = blockIdx.x * 128;
    mma_body<128, 128, 1, 0, 0, 0, 1>(
        Hh + (size_t)bm * DM, Hl + (size_t)bm * DM, DM,
        Wh + (size_t)bn * DM, Wl + (size_t)bn * DM, DM,
        b + bn, (const float*)0,
        (float*)0,
        Oh + (size_t)bm * DM + bn, Ol + (size_t)bm * DM + bn,
        DM, DM, 1.0f);
}

__global__ void __launch_bounds__(256, 2) mm_scores_kernel(
    const bf* __restrict__ Qh, const bf* __restrict__ Ql,
    const bf* __restrict__ Kh, const bf* __restrict__ Kl,
    float* __restrict__ P)
{
    const int kt = blockIdx.x, qt = blockIdx.y, h = blockIdx.z;
    if (kt > qt) return;
    mma_body<128, 128, 0, 0, 0, 1, 0>(
        Qh + (size_t)(qt * 128) * DM + h * DK, Ql + (size_t)(qt * 128) * DM + h * DK, DM,
        Kh + (size_t)(kt * 128) * DM + h * DK, Kl + (size_t)(kt * 128) * DM + h * DK, DM,
        (const float*)0, (const float*)0,
        P + (size_t)h * S * S + (size_t)(qt * 128) * S + kt * 128,
        (bf*)0, (bf*)0, S, DK, 0.125f);
}

__global__ void __launch_bounds__(256, 2) mm_ctx_kernel(
    const bf* __restrict__ Ph, const bf* __restrict__ Pl,
    const bf* __restrict__ Vth, const bf* __restrict__ Vtl,
    bf* __restrict__ Ch, bf* __restrict__ Cl)
{
    const int qt = blockIdx.x, h = blockIdx.y;
    mma_body<128, 64, 0, 0, 0, 0, 1>(
        Ph + (size_t)h * S * S + (size_t)(qt * 128) * S,
        Pl + (size_t)h * S * S + (size_t)(qt * 128) * S, S,
        Vth + (size_t)h * DK * S, Vtl + (size_t)h * DK * S, S,
        (const float*)0, (const float*)0,
        (float*)0,
        Ch + (size_t)(qt * 128) * DM + h * DK, Cl + (size_t)(qt * 128) * DM + h * DK,
        DM, (qt + 1) * 128, 1.0f);
}

// ================= fused weight prep =========================================
__global__ void __launch_bounds__(256) prep_all_kernel(
    const float* __restrict__ W_in, bf* __restrict__ wInh, bf* __restrict__ wInl,
    const float* __restrict__ Wq,  bf* __restrict__ wQh,  bf* __restrict__ wQl,
    const float* __restrict__ Wk,  bf* __restrict__ wKh,  bf* __restrict__ wKl,
    const float* __restrict__ Wv,  bf* __restrict__ wVh,  bf* __restrict__ wVl,
    const float* __restrict__ Wo,  bf* __restrict__ wOh,  bf* __restrict__ wOl,
    const float* __restrict__ W2,  bf* __restrict__ w2h,  bf* __restrict__ w2l,
    const float* __restrict__ Wf1, bf* __restrict__ wF1h, bf* __restrict__ wF1l,
    const float* __restrict__ Wf2, bf* __restrict__ wF2h, bf* __restrict__ wF2l)
{
    const int b = blockIdx.x;
    const float* W; bf* Bh; bf* Bl; int N, K, t;
    if (b < 6144) {
        const int wi = b >> 10;
        t = b & 1023;
        N = DM; K = DM;
        switch (wi) {
            case 0: W = W_in; Bh = wInh; Bl = wInl; break;
            case 1: W = Wq;   Bh = wQh;  Bl = wQl;  break;
            case 2: W = Wk;   Bh = wKh;  Bl = wKl;  break;
            case 3: W = Wv;   Bh = wVh;  Bl = wVl;  break;
            case 4: W = Wo;   Bh = wOh;  Bl = wOl;  break;
            default: W = W2;  Bh = w2h;  Bl = w2l;  break;
        }
    } else if (b < 10240) {
        t = b - 6144; N = DFF; K = DM;  W = Wf1; Bh = wF1h; Bl = wF1l;
    } else {
        t = b - 10240; N = DM; K = DFF; W = Wf2; Bh = wF2h; Bl = wF2l;
    }
    const int nx = N / 32;
    const int n0 = (t % nx) * 32, k0 = (t / nx) * 32;

    __shared__ float tt[32][33];
    const int tx = threadIdx.x & 31, ty = threadIdx.x >> 5;
#pragma unroll
    for (int i = 0; i < 4; i++) {
        int k = ty + i * 8;
        tt[k][tx] = W[(size_t)(k0 + k) * N + n0 + tx];
    }
    __syncthreads();
#pragma unroll
    for (int i = 0; i < 4; i++) {
        int n = ty + i * 8;
        float v = tt[tx][n];
        unsigned short h, l;
        split1(v, h, l);
        size_t o = (size_t)(n0 + n) * K + k0 + tx;
        Bh[o] = __ushort_as_bfloat16(h);
        Bl[o] = __ushort_as_bfloat16(l);
    }
}

// vt[h][c][s] = v[s][h*64+c]
__global__ void __launch_bounds__(256) prep_vt_kernel(
    const bf* __restrict__ Vh, const bf* __restrict__ Vl,
    bf* __restrict__ Vth, bf* __restrict__ Vtl)
{
    __shared__ bf th[32][33], tl[32][33];
    const int s0 = blockIdx.x * 32, c0 = blockIdx.y * 32, h = blockIdx.z;
    const int tx = threadIdx.x & 31, ty = threadIdx.x >> 5;
#pragma unroll
    for (int i = 0; i < 4; i++) {
        int s = ty + i * 8;
        th[s][tx] = Vh[(size_t)(s0 + s) * DM + h * DK + c0 + tx];
        tl[s][tx] = Vl[(size_t)(s0 + s) * DM + h * DK + c0 + tx];
    }
    __syncthreads();
#pragma unroll
    for (int i = 0; i < 4; i++) {
        int cc = ty + i * 8;
        size_t o = ((size_t)h * DK + c0 + cc) * S + s0 + tx;
        Vth[o] = th[tx][cc];
        Vtl[o] = tl[tx][cc];
    }
}

// ================= LN / softmax ==============================================
__device__ __forceinline__ float warp_sum(float v) {
#pragma unroll
    for (int o = 16; o > 0; o >>= 1) v += __shfl_xor_sync(0xffffffffu, v, o);
    return v;
}
__device__ __forceinline__ float warp_max(float v) {
#pragma unroll
    for (int o = 16; o > 0; o >>= 1) v = fmaxf(v, __shfl_xor_sync(0xffffffffu, v, o));
    return v;
}
__device__ __forceinline__ float block_sum(float v, float* red) {
    const int tid = threadIdx.x;
    v = warp_sum(v);
    if ((tid & 31) == 0) red[tid >> 5] = v;
    __syncthreads();
    float r = (tid < 8) ? red[tid] : 0.f;
    r = warp_sum(r);
    if (tid == 0) red[0] = r;
    __syncthreads();
    return red[0];
}
__device__ __forceinline__ float block_max(float v, float* red) {
    const int tid = threadIdx.x;
    v = warp_max(v);
    if ((tid & 31) == 0) red[tid >> 5] = v;
    __syncthreads();
    float r = (tid < 8) ? red[tid] : -3.0e38f;
    r = warp_max(r);
    if (tid == 0) red[0] = r;
    __syncthreads();
    return red[0];
}

template<int WF32>
__global__ void __launch_bounds__(256) ln_kernel(
    const float* __restrict__ x, const float* __restrict__ g, const float* __restrict__ b,
    float* __restrict__ y, bf* __restrict__ yh, bf* __restrict__ yl)
{
    const int row = blockIdx.x;
    const float4* xr = (const float4*)(x + (size_t)row * DM);
    __shared__ float red[8];
    const int tid = threadIdx.x;

    float4 xv = xr[tid];
    float s = xv.x + xv.y + xv.z + xv.w;
    const float mean = block_sum(s, red) * (1.f / DM);
    __syncthreads();

    float dx = xv.x - mean, dy = xv.y - mean, dz = xv.z - mean, dw = xv.w - mean;
    float v = dx * dx + dy * dy + dz * dz + dw * dw;
    const float var = block_sum(v, red) * (1.f / DM);
    const float inv = 1.f / (sqrtf(var) + 1e-6f);

    float4 gv = ((const float4*)g)[tid];
    float4 bv = ((const float4*)b)[tid];
    float4 o;
    o.x = gv.x * (dx * inv) + bv.x;
    o.y = gv.y * (dy * inv) + bv.y;
    o.z = gv.z * (dz * inv) + bv.z;
    o.w = gv.w * (dw * inv) + bv.w;
    if (WF32) ((float4*)(y + (size_t)row * DM))[tid] = o;

    uint32_t h0, l0, h1, l1;
    split2(o.x, o.y, h0, l0);
    split2(o.z, o.w, h1, l1);
    *(uint2*)(yh + (size_t)row * DM + tid * 4) = make_uint2(h0, h1);
    *(uint2*)(yl + (size_t)row * DM + tid * 4) = make_uint2(l0, l1);
}

__global__ void __launch_bounds__(256) softmax_kernel(
    float* __restrict__ P, bf* __restrict__ Ph, bf* __restrict__ Pl)
{
    const int row = blockIdx.x;          // h*S + q
    const int qi = row & (S - 1);
    float* p = P + (size_t)row * S;
    bf* ph = Ph + (size_t)row * S;
    bf* pl = Pl + (size_t)row * S;
    const int n = qi + 1;
    __shared__ float red[8];
    const int tid = threadIdx.x;

    float m = -3.0e38f;
    for (int j = tid; j < n; j += 256) m = fmaxf(m, p[j]);
    m = block_max(m, red);
    __syncthreads();

    float sum = 0.f;
    for (int j = tid; j < n; j += 256) { float e = expf(p[j] - m); p[j] = e; sum += e; }
    sum = block_sum(sum, red);
    const float inv = 1.f / sum;

    for (int j = tid; j < n; j += 256) {
        float val = p[j] * inv;
        p[j] = val;
        unsigned short h, l;
        split1(val, h, l);
        ph[j] = __ushort_as_bfloat16(h);
        pl[j] = __ushort_as_bfloat16(l);
    }
    const bf z = __ushort_as_bfloat16(0);
    for (int j = n + tid; j < S; j += 256) { p[j] = 0.f; ph[j] = z; pl[j] = z; }
}

// ================= host orchestration ========================================
#define GETP(var, sym) cudaGetSymbolAddress((void**)&var, sym)

extern "C" void kernel_launch(void* const* d_in, const int* in_sizes, int n_in,
                              void* d_out, int out_size)
{
    const float* x     = (const float*)d_in[0];
    const float* g1    = (const float*)d_in[1];
    const float* beta1 = (const float*)d_in[2];
    const float* W_in  = (const float*)d_in[3];
    const float* b_in  = (const float*)d_in[4];
    const float* Wq    = (const float*)d_in[5];
    const float* bq    = (const float*)d_in[6];
    const float* Wk    = (const float*)d_in[7];
    const float* bk    = (const float*)d_in[8];
    const float* Wv    = (const float*)d_in[9];
    const float* bv    = (const float*)d_in[10];
    const float* Wo    = (const float*)d_in[11];
    const float* bo    = (const float*)d_in[12];
    const float* W2    = (const float*)d_in[13];
    const float* b2    = (const float*)d_in[14];
    const float* g2    = (const float*)d_in[15];
    const float* beta2 = (const float*)d_in[16];
    const float* Wf1   = (const float*)d_in[17];
    const float* bf1   = (const float*)d_in[18];
    const float* Wf2   = (const float*)d_in[19];
    const float* bf2   = (const float*)d_in[20];

    float* out  = (float*)d_out;                       // [S, DM]
    float* attn = (float*)d_out + (size_t)S * DM;      // [NH, S, S]

    float *p_part1, *p_norm2;
    GETP(p_part1, g_part1); GETP(p_norm2, g_norm2);

    bf *n1h, *n1l, *hh, *hl, *qh, *ql, *kh, *kl, *vh, *vl, *vth, *vtl;
    bf *ctxh, *ctxl, *mhah, *mhal, *n2h, *n2l, *f1h, *f1l, *pph, *ppl;
    GETP(n1h, g_n1h); GETP(n1l, g_n1l);
    GETP(hh, g_hvh);  GETP(hl, g_hvl);
    GETP(qh, g_qh);   GETP(ql, g_ql);
    GETP(kh, g_kh);   GETP(kl, g_kl);
    GETP(vh, g_vh);   GETP(vl, g_vl);
    GETP(vth, g_vth); GETP(vtl, g_vtl);
    GETP(ctxh, g_ctxh); GETP(ctxl, g_ctxl);
    GETP(mhah, g_mhah); GETP(mhal, g_mhal);
    GETP(n2h, g_n2h); GETP(n2l, g_n2l);
    GETP(f1h, g_f1h); GETP(f1l, g_f1l);
    GETP(pph, g_ph);  GETP(ppl, g_pl);

    bf *wInh, *wInl, *wQh, *wQl, *wKh, *wKl, *wVh, *wVl, *wOh, *wOl, *w2h, *w2l;
    bf *wF1h, *wF1l, *wF2h, *wF2l;
    GETP(wInh, g_wInh); GETP(wInl, g_wInl);
    GETP(wQh, g_wQh);   GETP(wQl, g_wQl);
    GETP(wKh, g_wKh);   GETP(wKl, g_wKl);
    GETP(wVh, g_wVh);   GETP(wVl, g_wVl);
    GETP(wOh, g_wOh);   GETP(wOl, g_wOl);
    GETP(w2h, g_w2h);   GETP(w2l, g_w2l);
    GETP(wF1h, g_wF1h); GETP(wF1l, g_wF1l);
    GETP(wF2h, g_wF2h); GETP(wF2l, g_wF2l);

    // smem sizes per tile shape
    const int SM_D = 2 * (2 * 128 * PITCH + 2 * 128 * PITCH);   // 81920
    const int SM_C = 2 * (2 * 128 * PITCH + 2 * 64 * PITCH);    // 61440
    cudaFuncSetAttribute(mm_dense_kernel<0,0,0,1>, cudaFuncAttributeMaxDynamicSharedMemorySize, SM_D);
    cudaFuncSetAttribute(mm_dense_kernel<1,0,1,0>, cudaFuncAttributeMaxDynamicSharedMemorySize, SM_D);
    cudaFuncSetAttribute(mm_dense_kernel<0,1,0,1>, cudaFuncAttributeMaxDynamicSharedMemorySize, SM_D);
    cudaFuncSetAttribute(mm_qkv_kernel,    cudaFuncAttributeMaxDynamicSharedMemorySize, SM_D);
    cudaFuncSetAttribute(mm_scores_kernel, cudaFuncAttributeMaxDynamicSharedMemorySize, SM_D);
    cudaFuncSetAttribute(mm_ctx_kernel,    cudaFuncAttributeMaxDynamicSharedMemorySize, SM_C);

    // 0. all weight prep in one launch
    prep_all_kernel<<<14336, 256>>>(
        W_in, wInh, wInl, Wq, wQh, wQl, Wk, wKh, wKl, Wv, wVh, wVl,
        Wo, wOh, wOl, W2, w2h, w2l, Wf1, wF1h, wF1l, Wf2, wF2h, wF2l);

    // 1. LN1 -> hi/lo only
    ln_kernel<0><<<S, 256>>>(x, g1, beta1, nullptr, n1h, n1l);

    // 2. h = norm1 @ W_in + b_in  (hi/lo only)
    mm_dense_kernel<0,0,0,1><<<dim3(DM/128, S/128), 256, SM_D>>>(
        n1h, n1l, wInh, wInl, b_in, nullptr, nullptr, hh, hl, DM, DM);

    // 3. q/k/v
    mm_qkv_kernel<<<dim3(DM/128, S/128, 3), 256, SM_D>>>(
        hh, hl, wQh, wQl, bq, qh, ql, wKh, wKl, bk, kh, kl, wVh, wVl, bv, vh, vl);

    // 3b. V transpose per head
    prep_vt_kernel<<<dim3(S/32, DK/32, NH), 256>>>(vh, vl, vth, vtl);

    // 4. scores -> attn fp32; 5. softmax -> attn fp32 + P hi/lo
    mm_scores_kernel<<<dim3(S/128, S/128, NH), 256, SM_D>>>(qh, ql, kh, kl, attn);
    softmax_kernel<<<NH * S, 256>>>(attn, pph, ppl);

    // 6. ctx = P @ V (hi/lo only)
    mm_ctx_kernel<<<dim3(S/128, NH), 256, SM_C>>>(pph, ppl, vth, vtl, ctxh, ctxl);

    // 7. mha = ctx @ Wo + bo (hi/lo only)
    mm_dense_kernel<0,0,0,1><<<dim3(DM/128, S/128), 256, SM_D>>>(
        ctxh, ctxl, wOh, wOl, bo, nullptr, nullptr, mhah, mhal, DM, DM);

    // 8. part1 = x + mha @ W2 + b2 (fp32)
    mm_dense_kernel<1,0,1,0><<<dim3(DM/128, S/128), 256, SM_D>>>(
        mhah, mhal, w2h, w2l, b2, x, p_part1, nullptr, nullptr, DM, DM);

    // 9. LN2 -> fp32 + hi/lo
    ln_kernel<1><<<S, 256>>>(p_part1, g2, beta2, p_norm2, n2h, n2l);

    // 10. ff1 = relu(norm2 @ Wf1 + bf1) (hi/lo only)
    mm_dense_kernel<0,1,0,1><<<dim3(DFF/128, S/128), 256, SM_D>>>(
        n2h, n2l, wF1h, wF1l, bf1, nullptr, nullptr, f1h, f1l, DFF, DM);

    // 11. out = norm2 + ff1 @ Wf2 + bf2 (fp32)
    mm_dense_kernel<1,0,1,0><<<dim3(DM/128, S/128), 256, SM_D>>>(
        f1h, f1l, wF2h, wF2l, bf2, p_norm2, out, nullptr, nullptr, DM, DFF);
}

// round 15
// speedup vs baseline: 1.0831x; 1.0310x over previous
#include <cuda_runtime.h>
#include <cuda_bf16.h>
#include <math.h>
#include <stdint.h>

#define S    2048
#define DM   1024
#define NH   16
#define DK   64
#define DFF  4096

typedef __nv_bfloat16 bf;

// ---------------- fp32 scratch ----------------------------------------------
__device__ float g_part1[S * DM];
__device__ float g_norm2[S * DM];

// ---------------- bf16 hi/lo scratch ----------------------------------------
#define DECL2(name, n) __device__ __align__(128) bf name##h[n]; __device__ __align__(128) bf name##l[n];
DECL2(g_n1,  S * DM)
DECL2(g_hv,  S * DM)
DECL2(g_q,   S * DM)
DECL2(g_k,   S * DM)
DECL2(g_v,   S * DM)
DECL2(g_vt,  S * DM)          // [NH][DK][S]
DECL2(g_ctx, S * DM)
DECL2(g_mha, S * DM)
DECL2(g_n2,  S * DM)
DECL2(g_f1,  S * DFF)
DECL2(g_p,   (size_t)NH * S * S)
// weights (K-major [N][K])
DECL2(g_wIn, DM * DM)
DECL2(g_wQ,  DM * DM)
DECL2(g_wK,  DM * DM)
DECL2(g_wV,  DM * DM)
DECL2(g_wO,  DM * DM)
DECL2(g_w2,  DM * DM)
DECL2(g_wF1, DM * DFF)
DECL2(g_wF2, DFF * DM)

// ================= helpers ===================================================
__device__ __forceinline__ uint32_t smem_u32(const void* p) {
    uint32_t a;
    asm("{ .reg .u64 t; cvta.to.shared.u64 t, %1; cvt.u32.u64 %0, t; }" : "=r"(a) : "l"(p));
    return a;
}
__device__ __forceinline__ void split2(float a, float b, uint32_t& hi, uint32_t& lo) {
    unsigned short ha = __bfloat16_as_ushort(__float2bfloat16_rn(a));
    unsigned short hb = __bfloat16_as_ushort(__float2bfloat16_rn(b));
    float fa = __bfloat162float(__ushort_as_bfloat16(ha));
    float fb = __bfloat162float(__ushort_as_bfloat16(hb));
    unsigned short la = __bfloat16_as_ushort(__float2bfloat16_rn(a - fa));
    unsigned short lb = __bfloat16_as_ushort(__float2bfloat16_rn(b - fb));
    hi = ((uint32_t)hb << 16) | ha;
    lo = ((uint32_t)lb << 16) | la;
}
__device__ __forceinline__ void split1(float a, unsigned short& h, unsigned short& l) {
    h = __bfloat16_as_ushort(__float2bfloat16_rn(a));
    l = __bfloat16_as_ushort(__float2bfloat16_rn(a - __bfloat162float(__ushort_as_bfloat16(h))));
}
__device__ __forceinline__ void ldsm_x4(uint32_t& a0, uint32_t& a1, uint32_t& a2, uint32_t& a3,
                                        uint32_t addr) {
    asm volatile("ldmatrix.sync.aligned.m8n8.x4.shared.b16 {%0,%1,%2,%3}, [%4];"
                 : "=r"(a0), "=r"(a1), "=r"(a2), "=r"(a3) : "r"(addr));
}
__device__ __forceinline__ void mma16816(float* d, const uint32_t* a, const uint32_t* b) {
    asm volatile("mma.sync.aligned.m16n8k16.row.col.f32.bf16.bf16.f32 "
                 "{%0,%1,%2,%3}, {%4,%5,%6,%7}, {%8,%9}, {%0,%1,%2,%3};"
                 : "+f"(d[0]), "+f"(d[1]), "+f"(d[2]), "+f"(d[3])
                 : "r"(a[0]), "r"(a[1]), "r"(a[2]), "r"(a[3]), "r"(b[0]), "r"(b[1]));
}
__device__ __forceinline__ void cpa16(uint32_t saddr, const void* g) {
    asm volatile("cp.async.ca.shared.global [%0], [%1], 16;" :: "r"(saddr), "l"(g));
}
#define CP_COMMIT() asm volatile("cp.async.commit_group;" ::: "memory")

#define PITCH 80   // bytes per smem row (32 bf16 data + pad); ldmatrix conflict-free

// ================= pipelined HMMA GEMM body ==================================
// C[BM x BN] = alpha*(A@B) (+bias)(+res)(+relu); A/B pre-split bf16 hi/lo,
// both K-major. 2-stage cp.async pipeline, BK=32. NWARP warps, WN=2, WM=NWARP/2.
// B hi/lo merged ldmatrix.x4 (lanes 0-15 hi, 16-31 lo).
template<int BM, int BN, int NWARP, int HASBIAS, int RES, int RELU, int WF32, int WSPLIT>
__device__ __forceinline__ void mma_body(
    const bf* __restrict__ Ah, const bf* __restrict__ Al, int lda,
    const bf* __restrict__ Bh, const bf* __restrict__ Bl, int ldb,
    const float* __restrict__ bias, const float* __restrict__ Dres,
    float* __restrict__ C, bf* __restrict__ Ch, bf* __restrict__ Cl,
    int ldc, int K, float alpha)
{
    extern __shared__ __align__(128) char sm[];
    constexpr int THREADS = NWARP * 32;
    constexpr int ASZ = BM * PITCH;
    constexpr int BSZ = BN * PITCH;
    constexpr int STAGE = 2 * ASZ + 2 * BSZ;

    const int tid = threadIdx.x, lane = tid & 31, wid = tid >> 5;
    constexpr int WN  = 2;
    constexpr int WM  = NWARP / 2;
    constexpr int WTM = BM / WM;
    constexpr int WTN = BN / WN;
    constexpr int MI  = WTM / 16;
    constexpr int NI  = WTN / 8;
    const int wm = wid >> 1, wn = wid & 1;
    const uint32_t sb = smem_u32(sm);

    float acc[MI][NI][4];
#pragma unroll
    for (int i = 0; i < MI; i++)
#pragma unroll
        for (int j = 0; j < NI; j++)
#pragma unroll
            for (int r = 0; r < 4; r++) acc[i][j][r] = 0.f;

    const int NC = K >> 5;

    auto issue = [&](int st, int c) {
        const uint32_t base = sb + st * STAGE;
#pragma unroll
        for (int it = 0; it < BM * 8 / THREADS; it++) {     // A: BM rows x4 seg x2 arr
            int idx = it * THREADS + tid;
            int arr = idx / (BM * 4);
            int rem = idx % (BM * 4);
            int r = rem >> 2, sg = rem & 3;
            const bf* g = (arr ? Al : Ah) + (size_t)r * lda + (size_t)c * 32 + sg * 8;
            cpa16(base + arr * ASZ + r * PITCH + sg * 16, g);
        }
#pragma unroll
        for (int it = 0; it < BN * 8 / THREADS; it++) {     // B
            int idx = it * THREADS + tid;
            int arr = idx / (BN * 4);
            int rem = idx % (BN * 4);
            int r = rem >> 2, sg = rem & 3;
            const bf* g = (arr ? Bl : Bh) + (size_t)r * ldb + (size_t)c * 32 + sg * 8;
            cpa16(base + 2 * ASZ + arr * BSZ + r * PITCH + sg * 16, g);
        }
    };

    issue(0, 0);
    CP_COMMIT();

    for (int c = 0; c < NC; c++) {
        const int st = c & 1;
        const bool pf = (c + 1 < NC);
        if (pf) { issue(st ^ 1, c + 1); CP_COMMIT(); }
        if (pf) { asm volatile("cp.async.wait_group 1;" ::: "memory"); }
        else    { asm volatile("cp.async.wait_group 0;" ::: "memory"); }
        __syncthreads();

        const uint32_t aH = sb + st * STAGE;
        const uint32_t aL = aH + ASZ;
        const uint32_t bH = aH + 2 * ASZ;

#pragma unroll
        for (int ks = 0; ks < 2; ks++) {
            uint32_t Af[MI][4], Bf[NI][4];
            const int acol2 = (ks * 16 + ((lane >> 4) << 3)) * 2;
            const int bcol2 = (ks * 16 + (((lane >> 3) & 1) << 3)) * 2;
            const uint32_t bsel = (uint32_t)(lane >> 4) * BSZ;
#pragma unroll
            for (int ni = 0; ni < NI; ni++) {
                uint32_t o = (uint32_t)((wn * WTN + ni * 8 + (lane & 7)) * PITCH + bcol2) + bsel;
                ldsm_x4(Bf[ni][0], Bf[ni][1], Bf[ni][2], Bf[ni][3], bH + o);
            }
#pragma unroll
            for (int mi = 0; mi < MI; mi++) {
                uint32_t o = (uint32_t)((wm * WTM + mi * 16 + (lane & 15)) * PITCH + acol2);
                ldsm_x4(Af[mi][0], Af[mi][1], Af[mi][2], Af[mi][3], aH + o);
            }
#pragma unroll
            for (int mi = 0; mi < MI; mi++)
#pragma unroll
                for (int ni = 0; ni < NI; ni++) {
                    mma16816(acc[mi][ni], Af[mi], &Bf[ni][0]);   // hi*hi
                    mma16816(acc[mi][ni], Af[mi], &Bf[ni][2]);   // hi*lo
                }
#pragma unroll
            for (int mi = 0; mi < MI; mi++) {
                uint32_t o = (uint32_t)((wm * WTM + mi * 16 + (lane & 15)) * PITCH + acol2);
                ldsm_x4(Af[mi][0], Af[mi][1], Af[mi][2], Af[mi][3], aL + o);
            }
#pragma unroll
            for (int mi = 0; mi < MI; mi++)
#pragma unroll
                for (int ni = 0; ni < NI; ni++)
                    mma16816(acc[mi][ni], Af[mi], &Bf[ni][0]);   // lo*hi
        }
        __syncthreads();
    }

    // ---- epilogue ----
    const int groupID = lane >> 2, tig = lane & 3;
#pragma unroll
    for (int mi = 0; mi < MI; mi++) {
        const int r0 = wm * WTM + mi * 16 + groupID;
        const int r1 = r0 + 8;
#pragma unroll
        for (int ni = 0; ni < NI; ni++) {
            const int col = wn * WTN + ni * 8 + tig * 2;
            float2 v0, v1;
            v0.x = acc[mi][ni][0] * alpha; v0.y = acc[mi][ni][1] * alpha;
            v1.x = acc[mi][ni][2] * alpha; v1.y = acc[mi][ni][3] * alpha;
            if (HASBIAS) {
                v0.x += bias[col]; v0.y += bias[col + 1];
                v1.x += bias[col]; v1.y += bias[col + 1];
            }
            if (RES) {
                v0.x += Dres[(size_t)r0 * ldc + col];
                v0.y += Dres[(size_t)r0 * ldc + col + 1];
                v1.x += Dres[(size_t)r1 * ldc + col];
                v1.y += Dres[(size_t)r1 * ldc + col + 1];
            }
            if (RELU) {
                v0.x = fmaxf(v0.x, 0.f); v0.y = fmaxf(v0.y, 0.f);
                v1.x = fmaxf(v1.x, 0.f); v1.y = fmaxf(v1.y, 0.f);
            }
            if (WF32) {
                *(float2*)(C + (size_t)r0 * ldc + col) = v0;
                *(float2*)(C + (size_t)r1 * ldc + col) = v1;
            }
            if (WSPLIT) {
                uint32_t hi, lo;
                split2(v0.x, v0.y, hi, lo);
                *(uint32_t*)(Ch + (size_t)r0 * ldc + col) = hi;
                *(uint32_t*)(Cl + (size_t)r0 * ldc + col) = lo;
                split2(v1.x, v1.y, hi, lo);
                *(uint32_t*)(Ch + (size_t)r1 * ldc + col) = hi;
                *(uint32_t*)(Cl + (size_t)r1 * ldc + col) = lo;
            }
        }
    }
}

// ================= GEMM kernels ==============================================
// BN=128 kernels: 4 fat warps (128 threads, 64x64 warp tiles)
template<int RES, int RELU, int WF32, int WSPLIT>
__global__ void __launch_bounds__(128, 2) mm_dense_kernel(
    const bf* __restrict__ Ah, const bf* __restrict__ Al,
    const bf* __restrict__ Bh, const bf* __restrict__ Bl,
    const float* __restrict__ bias, const float* __restrict__ Dres,
    float* __restrict__ C, bf* __restrict__ Ch, bf* __restrict__ Cl,
    int N, int K)
{
    const int bm = blockIdx.y * 128, bn = blockIdx.x * 128;
    mma_body<128, 128, 4, 1, RES, RELU, WF32, WSPLIT>(
        Ah + (size_t)bm * K, Al + (size_t)bm * K, K,
        Bh + (size_t)bn * K, Bl + (size_t)bn * K, K,
        bias + bn,
        RES ? (Dres + (size_t)bm * N + bn) : (const float*)0,
        WF32 ? (C + (size_t)bm * N + bn) : (float*)0,
        WSPLIT ? (Ch + (size_t)bm * N + bn) : (bf*)0,
        WSPLIT ? (Cl + (size_t)bm * N + bn) : (bf*)0,
        N, K, 1.0f);
}

__global__ void __launch_bounds__(128, 2) mm_qkv_kernel(
    const bf* __restrict__ Hh, const bf* __restrict__ Hl,
    const bf* __restrict__ WQh, const bf* __restrict__ WQl, const float* __restrict__ bq,
    bf* __restrict__ Qh, bf* __restrict__ Ql,
    const bf* __restrict__ WKh, const bf* __restrict__ WKl, const float* __restrict__ bk,
    bf* __restrict__ Kh, bf* __restrict__ Kl,
    const bf* __restrict__ WVh, const bf* __restrict__ WVl, const float* __restrict__ bv,
    bf* __restrict__ Vh, bf* __restrict__ Vl)
{
    const bf *Wh, *Wl; const float* b; bf *Oh, *Ol;
    if (blockIdx.z == 0)      { Wh = WQh; Wl = WQl; b = bq; Oh = Qh; Ol = Ql; }
    else if (blockIdx.z == 1) { Wh = WKh; Wl = WKl; b = bk; Oh = Kh; Ol = Kl; }
    else                      { Wh = WVh; Wl = WVl; b = bv; Oh = Vh; Ol = Vl; }
    const int bm = blockIdx.y * 128, bn = blockIdx.x * 128;
    mma_body<128, 128, 4, 1, 0, 0, 0, 1>(
        Hh + (size_t)bm * DM, Hl + (size_t)bm * DM, DM,
        Wh + (size_t)bn * DM, Wl + (size_t)bn * DM, DM,
        b + bn, (const float*)0,
        (float*)0,
        Oh + (size_t)bm * DM + bn, Ol + (size_t)bm * DM + bn,
        DM, DM, 1.0f);
}

__global__ void __launch_bounds__(128, 2) mm_scores_kernel(
    const bf* __restrict__ Qh, const bf* __restrict__ Ql,
    const bf* __restrict__ Kh, const bf* __restrict__ Kl,
    float* __restrict__ P)
{
    const int kt = blockIdx.x, qt = blockIdx.y, h = blockIdx.z;
    if (kt > qt) return;
    mma_body<128, 128, 4, 0, 0, 0, 1, 0>(
        Qh + (size_t)(qt * 128) * DM + h * DK, Ql + (size_t)(qt * 128) * DM + h * DK, DM,
        Kh + (size_t)(kt * 128) * DM + h * DK, Kl + (size_t)(kt * 128) * DM + h * DK, DM,
        (const float*)0, (const float*)0,
        P + (size_t)h * S * S + (size_t)(qt * 128) * S + kt * 128,
        (bf*)0, (bf*)0, S, DK, 0.125f);
}

// ctx keeps 8 warps (BN=64)
__global__ void __launch_bounds__(256, 2) mm_ctx_kernel(
    const bf* __restrict__ Ph, const bf* __restrict__ Pl,
    const bf* __restrict__ Vth, const bf* __restrict__ Vtl,
    bf* __restrict__ Ch, bf* __restrict__ Cl)
{
    const int qt = blockIdx.x, h = blockIdx.y;
    mma_body<128, 64, 8, 0, 0, 0, 0, 1>(
        Ph + (size_t)h * S * S + (size_t)(qt * 128) * S,
        Pl + (size_t)h * S * S + (size_t)(qt * 128) * S, S,
        Vth + (size_t)h * DK * S, Vtl + (size_t)h * DK * S, S,
        (const float*)0, (const float*)0,
        (float*)0,
        Ch + (size_t)(qt * 128) * DM + h * DK, Cl + (size_t)(qt * 128) * DM + h * DK,
        DM, (qt + 1) * 128, 1.0f);
}

// ================= fused weight prep =========================================
__global__ void __launch_bounds__(256) prep_all_kernel(
    const float* __restrict__ W_in, bf* __restrict__ wInh, bf* __restrict__ wInl,
    const float* __restrict__ Wq,  bf* __restrict__ wQh,  bf* __restrict__ wQl,
    const float* __restrict__ Wk,  bf* __restrict__ wKh,  bf* __restrict__ wKl,
    const float* __restrict__ Wv,  bf* __restrict__ wVh,  bf* __restrict__ wVl,
    const float* __restrict__ Wo,  bf* __restrict__ wOh,  bf* __restrict__ wOl,
    const float* __restrict__ W2,  bf* __restrict__ w2h,  bf* __restrict__ w2l,
    const float* __restrict__ Wf1, bf* __restrict__ wF1h, bf* __restrict__ wF1l,
    const float* __restrict__ Wf2, bf* __restrict__ wF2h, bf* __restrict__ wF2l)
{
    const int b = blockIdx.x;
    const float* W; bf* Bh; bf* Bl; int N, K, t;
    if (b < 6144) {
        const int wi = b >> 10;
        t = b & 1023;
        N = DM; K = DM;
        switch (wi) {
            case 0: W = W_in; Bh = wInh; Bl = wInl; break;
            case 1: W = Wq;   Bh = wQh;  Bl = wQl;  break;
            case 2: W = Wk;   Bh = wKh;  Bl = wKl;  break;
            case 3: W = Wv;   Bh = wVh;  Bl = wVl;  break;
            case 4: W = Wo;   Bh = wOh;  Bl = wOl;  break;
            default: W = W2;  Bh = w2h;  Bl = w2l;  break;
        }
    } else if (b < 10240) {
        t = b - 6144; N = DFF; K = DM;  W = Wf1; Bh = wF1h; Bl = wF1l;
    } else {
        t = b - 10240; N = DM; K = DFF; W = Wf2; Bh = wF2h; Bl = wF2l;
    }
    const int nx = N / 32;
    const int n0 = (t % nx) * 32, k0 = (t / nx) * 32;

    __shared__ float tt[32][33];
    const int tx = threadIdx.x & 31, ty = threadIdx.x >> 5;
#pragma unroll
    for (int i = 0; i < 4; i++) {
        int k = ty + i * 8;
        tt[k][tx] = W[(size_t)(k0 + k) * N + n0 + tx];
    }
    __syncthreads();
#pragma unroll
    for (int i = 0; i < 4; i++) {
        int n = ty + i * 8;
        float v = tt[tx][n];
        unsigned short h, l;
        split1(v, h, l);
        size_t o = (size_t)(n0 + n) * K + k0 + tx;
        Bh[o] = __ushort_as_bfloat16(h);
        Bl[o] = __ushort_as_bfloat16(l);
    }
}

// vt[h][c][s] = v[s][h*64+c]
__global__ void __launch_bounds__(256) prep_vt_kernel(
    const bf* __restrict__ Vh, const bf* __restrict__ Vl,
    bf* __restrict__ Vth, bf* __restrict__ Vtl)
{
    __shared__ bf th[32][33], tl[32][33];
    const int s0 = blockIdx.x * 32, c0 = blockIdx.y * 32, h = blockIdx.z;
    const int tx = threadIdx.x & 31, ty = threadIdx.x >> 5;
#pragma unroll
    for (int i = 0; i < 4; i++) {
        int s = ty + i * 8;
        th[s][tx] = Vh[(size_t)(s0 + s) * DM + h * DK + c0 + tx];
        tl[s][tx] = Vl[(size_t)(s0 + s) * DM + h * DK + c0 + tx];
    }
    __syncthreads();
#pragma unroll
    for (int i = 0; i < 4; i++) {
        int cc = ty + i * 8;
        size_t o = ((size_t)h * DK + c0 + cc) * S + s0 + tx;
        Vth[o] = th[tx][cc];
        Vtl[o] = tl[tx][cc];
    }
}

// ================= LN / softmax ==============================================
__device__ __forceinline__ float warp_sum(float v) {
#pragma unroll
    for (int o = 16; o > 0; o >>= 1) v += __shfl_xor_sync(0xffffffffu, v, o);
    return v;
}
__device__ __forceinline__ float warp_max(float v) {
#pragma unroll
    for (int o = 16; o > 0; o >>= 1) v = fmaxf(v, __shfl_xor_sync(0xffffffffu, v, o));
    return v;
}
__device__ __forceinline__ float block_sum(float v, float* red) {
    const int tid = threadIdx.x;
    v = warp_sum(v);
    if ((tid & 31) == 0) red[tid >> 5] = v;
    __syncthreads();
    float r = (tid < 8) ? red[tid] : 0.f;
    r = warp_sum(r);
    if (tid == 0) red[0] = r;
    __syncthreads();
    return red[0];
}
__device__ __forceinline__ float block_max(float v, float* red) {
    const int tid = threadIdx.x;
    v = warp_max(v);
    if ((tid & 31) == 0) red[tid >> 5] = v;
    __syncthreads();
    float r = (tid < 8) ? red[tid] : -3.0e38f;
    r = warp_max(r);
    if (tid == 0) red[0] = r;
    __syncthreads();
    return red[0];
}

template<int WF32>
__global__ void __launch_bounds__(256) ln_kernel(
    const float* __restrict__ x, const float* __restrict__ g, const float* __restrict__ b,
    float* __restrict__ y, bf* __restrict__ yh, bf* __restrict__ yl)
{
    const int row = blockIdx.x;
    const float4* xr = (const float4*)(x + (size_t)row * DM);
    __shared__ float red[8];
    const int tid = threadIdx.x;

    float4 xv = xr[tid];
    float s = xv.x + xv.y + xv.z + xv.w;
    const float mean = block_sum(s, red) * (1.f / DM);
    __syncthreads();

    float dx = xv.x - mean, dy = xv.y - mean, dz = xv.z - mean, dw = xv.w - mean;
    float v = dx * dx + dy * dy + dz * dz + dw * dw;
    const float var = block_sum(v, red) * (1.f / DM);
    const float inv = 1.f / (sqrtf(var) + 1e-6f);

    float4 gv = ((const float4*)g)[tid];
    float4 bv = ((const float4*)b)[tid];
    float4 o;
    o.x = gv.x * (dx * inv) + bv.x;
    o.y = gv.y * (dy * inv) + bv.y;
    o.z = gv.z * (dz * inv) + bv.z;
    o.w = gv.w * (dw * inv) + bv.w;
    if (WF32) ((float4*)(y + (size_t)row * DM))[tid] = o;

    uint32_t h0, l0, h1, l1;
    split2(o.x, o.y, h0, l0);
    split2(o.z, o.w, h1, l1);
    *(uint2*)(yh + (size_t)row * DM + tid * 4) = make_uint2(h0, h1);
    *(uint2*)(yl + (size_t)row * DM + tid * 4) = make_uint2(l0, l1);
}

__global__ void __launch_bounds__(256) softmax_kernel(
    float* __restrict__ P, bf* __restrict__ Ph, bf* __restrict__ Pl)
{
    const int row = blockIdx.x;          // h*S + q
    const int qi = row & (S - 1);
    float* p = P + (size_t)row * S;
    bf* ph = Ph + (size_t)row * S;
    bf* pl = Pl + (size_t)row * S;
    const int n = qi + 1;
    const int bnd = ((qi >> 7) + 1) << 7;    // ctx reads hi/lo only up to tile boundary
    __shared__ float red[8];
    const int tid = threadIdx.x;

    float m = -3.0e38f;
    for (int j = tid; j < n; j += 256) m = fmaxf(m, p[j]);
    m = block_max(m, red);
    __syncthreads();

    float sum = 0.f;
    for (int j = tid; j < n; j += 256) { float e = expf(p[j] - m); p[j] = e; sum += e; }
    sum = block_sum(sum, red);
    const float inv = 1.f / sum;

    for (int j = tid; j < n; j += 256) {
        float val = p[j] * inv;
        p[j] = val;
        unsigned short h, l;
        split1(val, h, l);
        ph[j] = __ushort_as_bfloat16(h);
        pl[j] = __ushort_as_bfloat16(l);
    }
    const bf z = __ushort_as_bfloat16(0);
    for (int j = n + tid; j < bnd; j += 256) { ph[j] = z; pl[j] = z; }
    for (int j = n + tid; j < S; j += 256) p[j] = 0.f;   // fp32 zeros: full row (output)
}

// ================= host orchestration ========================================
#define GETP(var, sym) cudaGetSymbolAddress((void**)&var, sym)

extern "C" void kernel_launch(void* const* d_in, const int* in_sizes, int n_in,
                              void* d_out, int out_size)
{
    const float* x     = (const float*)d_in[0];
    const float* g1    = (const float*)d_in[1];
    const float* beta1 = (const float*)d_in[2];
    const float* W_in  = (const float*)d_in[3];
    const float* b_in  = (const float*)d_in[4];
    const float* Wq    = (const float*)d_in[5];
    const float* bq    = (const float*)d_in[6];
    const float* Wk    = (const float*)d_in[7];
    const float* bk    = (const float*)d_in[8];
    const float* Wv    = (const float*)d_in[9];
    const float* bv    = (const float*)d_in[10];
    const float* Wo    = (const float*)d_in[11];
    const float* bo    = (const float*)d_in[12];
    const float* W2    = (const float*)d_in[13];
    const float* b2    = (const float*)d_in[14];
    const float* g2    = (const float*)d_in[15];
    const float* beta2 = (const float*)d_in[16];
    const float* Wf1   = (const float*)d_in[17];
    const float* bf1   = (const float*)d_in[18];
    const float* Wf2   = (const float*)d_in[19];
    const float* bf2   = (const float*)d_in[20];

    float* out  = (float*)d_out;                       // [S, DM]
    float* attn = (float*)d_out + (size_t)S * DM;      // [NH, S, S]

    float *p_part1, *p_norm2;
    GETP(p_part1, g_part1); GETP(p_norm2, g_norm2);

    bf *n1h, *n1l, *hh, *hl, *qh, *ql, *kh, *kl, *vh, *vl, *vth, *vtl;
    bf *ctxh, *ctxl, *mhah, *mhal, *n2h, *n2l, *f1h, *f1l, *pph, *ppl;
    GETP(n1h, g_n1h); GETP(n1l, g_n1l);
    GETP(hh, g_hvh);  GETP(hl, g_hvl);
    GETP(qh, g_qh);   GETP(ql, g_ql);
    GETP(kh, g_kh);   GETP(kl, g_kl);
    GETP(vh, g_vh);   GETP(vl, g_vl);
    GETP(vth, g_vth); GETP(vtl, g_vtl);
    GETP(ctxh, g_ctxh); GETP(ctxl, g_ctxl);
    GETP(mhah, g_mhah); GETP(mhal, g_mhal);
    GETP(n2h, g_n2h); GETP(n2l, g_n2l);
    GETP(f1h, g_f1h); GETP(f1l, g_f1l);
    GETP(pph, g_ph);  GETP(ppl, g_pl);

    bf *wInh, *wInl, *wQh, *wQl, *wKh, *wKl, *wVh, *wVl, *wOh, *wOl, *w2h, *w2l;
    bf *wF1h, *wF1l, *wF2h, *wF2l;
    GETP(wInh, g_wInh); GETP(wInl, g_wInl);
    GETP(wQh, g_wQh);   GETP(wQl, g_wQl);
    GETP(wKh, g_wKh);   GETP(wKl, g_wKl);
    GETP(wVh, g_wVh);   GETP(wVl, g_wVl);
    GETP(wOh, g_wOh);   GETP(wOl, g_wOl);
    GETP(w2h, g_w2h);   GETP(w2l, g_w2l);
    GETP(wF1h, g_wF1h); GETP(wF1l, g_wF1l);
    GETP(wF2h, g_wF2h); GETP(wF2l, g_wF2l);

    // smem sizes per tile shape
    const int SM_D = 2 * (2 * 128 * PITCH + 2 * 128 * PITCH);   // 81920
    const int SM_C = 2 * (2 * 128 * PITCH + 2 * 64 * PITCH);    // 61440
    cudaFuncSetAttribute(mm_dense_kernel<0,0,0,1>, cudaFuncAttributeMaxDynamicSharedMemorySize, SM_D);
    cudaFuncSetAttribute(mm_dense_kernel<1,0,1,0>, cudaFuncAttributeMaxDynamicSharedMemorySize, SM_D);
    cudaFuncSetAttribute(mm_dense_kernel<0,1,0,1>, cudaFuncAttributeMaxDynamicSharedMemorySize, SM_D);
    cudaFuncSetAttribute(mm_qkv_kernel,    cudaFuncAttributeMaxDynamicSharedMemorySize, SM_D);
    cudaFuncSetAttribute(mm_scores_kernel, cudaFuncAttributeMaxDynamicSharedMemorySize, SM_D);
    cudaFuncSetAttribute(mm_ctx_kernel,    cudaFuncAttributeMaxDynamicSharedMemorySize, SM_C);

    // 0. all weight prep in one launch
    prep_all_kernel<<<14336, 256>>>(
        W_in, wInh, wInl, Wq, wQh, wQl, Wk, wKh, wKl, Wv, wVh, wVl,
        Wo, wOh, wOl, W2, w2h, w2l, Wf1, wF1h, wF1l, Wf2, wF2h, wF2l);

    // 1. LN1 -> hi/lo only
    ln_kernel<0><<<S, 256>>>(x, g1, beta1, nullptr, n1h, n1l);

    // 2. h = norm1 @ W_in + b_in  (hi/lo only)
    mm_dense_kernel<0,0,0,1><<<dim3(DM/128, S/128), 128, SM_D>>>(
        n1h, n1l, wInh, wInl, b_in, nullptr, nullptr, hh, hl, DM, DM);

    // 3. q/k/v
    mm_qkv_kernel<<<dim3(DM/128, S/128, 3), 128, SM_D>>>(
        hh, hl, wQh, wQl, bq, qh, ql, wKh, wKl, bk, kh, kl, wVh, wVl, bv, vh, vl);

    // 3b. V transpose per head
    prep_vt_kernel<<<dim3(S/32, DK/32, NH), 256>>>(vh, vl, vth, vtl);

    // 4. scores -> attn fp32; 5. softmax -> attn fp32 + P hi/lo
    mm_scores_kernel<<<dim3(S/128, S/128, NH), 128, SM_D>>>(qh, ql, kh, kl, attn);
    softmax_kernel<<<NH * S, 256>>>(attn, pph, ppl);

    // 6. ctx = P @ V (hi/lo only)
    mm_ctx_kernel<<<dim3(S/128, NH), 256, SM_C>>>(pph, ppl, vth, vtl, ctxh, ctxl);

    // 7. mha = ctx @ Wo + bo (hi/lo only)
    mm_dense_kernel<0,0,0,1><<<dim3(DM/128, S/128), 128, SM_D>>>(
        ctxh, ctxl, wOh, wOl, bo, nullptr, nullptr, mhah, mhal, DM, DM);

    // 8. part1 = x + mha @ W2 + b2 (fp32)
    mm_dense_kernel<1,0,1,0><<<dim3(DM/128, S/128), 128, SM_D>>>(
        mhah, mhal, w2h, w2l, b2, x, p_part1, nullptr, nullptr, DM, DM);

    // 9. LN2 -> fp32 + hi/lo
    ln_kernel<1><<<S, 256>>>(p_part1, g2, beta2, p_norm2, n2h, n2l);

    // 10. ff1 = relu(norm2 @ Wf1 + bf1) (hi/lo only)
    mm_dense_kernel<0,1,0,1><<<dim3(DFF/128, S/128), 128, SM_D>>>(
        n2h, n2l, wF1h, wF1l, bf1, nullptr, nullptr, f1h, f1l, DFF, DM);

    // 11. out = norm2 + ff1 @ Wf2 + bf2 (fp32)
    mm_dense_kernel<1,0,1,0><<<dim3(DM/128, S/128), 128, SM_D>>>(
        f1h, f1l, wF2h, wF2l, bf2, p_norm2, out, nullptr, nullptr, DM, DFF);
}

// round 17
// speedup vs baseline: 1.4758x; 1.3626x over previous
#include <cuda_runtime.h>
#include <cuda_fp16.h>
#include <math.h>
#include <stdint.h>

#define S    2048
#define DM   1024
#define NH   16
#define DK   64
#define DFF  4096

typedef __half hf;

// ---------------- fp32 scratch ----------------------------------------------
__device__ float g_part1[S * DM];
__device__ float g_norm2[S * DM];

// ---------------- fp16 scratch ----------------------------------------------
// A-side tensors: hi only. B-side tensors: hi + lo.
#define DECL1(name, n) __device__ __align__(128) hf name##h[n];
#define DECL2(name, n) __device__ __align__(128) hf name##h[n]; __device__ __align__(128) hf name##l[n];
DECL1(g_n1,  S * DM)
DECL1(g_hv,  S * DM)
DECL1(g_q,   S * DM)
DECL2(g_k,   S * DM)
DECL2(g_v,   S * DM)
DECL2(g_vt,  S * DM)          // [NH][DK][S]
DECL1(g_ctx, S * DM)
DECL1(g_mha, S * DM)
DECL1(g_n2,  S * DM)
DECL1(g_f1,  S * DFF)
DECL1(g_p,   (size_t)NH * S * S)
// weights (K-major [N][K]) hi+lo
DECL2(g_wIn, DM * DM)
DECL2(g_wQ,  DM * DM)
DECL2(g_wK,  DM * DM)
DECL2(g_wV,  DM * DM)
DECL2(g_wO,  DM * DM)
DECL2(g_w2,  DM * DM)
DECL2(g_wF1, DM * DFF)
DECL2(g_wF2, DFF * DM)

// ================= helpers ===================================================
__device__ __forceinline__ uint32_t smem_u32(const void* p) {
    uint32_t a;
    asm("{ .reg .u64 t; cvta.to.shared.u64 t, %1; cvt.u32.u64 %0, t; }" : "=r"(a) : "l"(p));
    return a;
}
__device__ __forceinline__ unsigned short h2u(hf x) { return __half_as_ushort(x); }

// fp32 -> fp16 hi (+lo)
__device__ __forceinline__ uint32_t pack_hi2(float a, float b) {
    return ((uint32_t)h2u(__float2half_rn(b)) << 16) | h2u(__float2half_rn(a));
}
__device__ __forceinline__ void split2h(float a, float b, uint32_t& hi, uint32_t& lo) {
    hf ha = __float2half_rn(a), hb = __float2half_rn(b);
    hf la = __float2half_rn(a - __half2float(ha));
    hf lb = __float2half_rn(b - __half2float(hb));
    hi = ((uint32_t)h2u(hb) << 16) | h2u(ha);
    lo = ((uint32_t)h2u(lb) << 16) | h2u(la);
}
__device__ __forceinline__ void split1h(float a, hf& h, hf& l) {
    h = __float2half_rn(a);
    l = __float2half_rn(a - __half2float(h));
}
__device__ __forceinline__ void ldsm_x4(uint32_t& a0, uint32_t& a1, uint32_t& a2, uint32_t& a3,
                                        uint32_t addr) {
    asm volatile("ldmatrix.sync.aligned.m8n8.x4.shared.b16 {%0,%1,%2,%3}, [%4];"
                 : "=r"(a0), "=r"(a1), "=r"(a2), "=r"(a3) : "r"(addr));
}
__device__ __forceinline__ void mma16816(float* d, const uint32_t* a, const uint32_t* b) {
    asm volatile("mma.sync.aligned.m16n8k16.row.col.f32.f16.f16.f32 "
                 "{%0,%1,%2,%3}, {%4,%5,%6,%7}, {%8,%9}, {%0,%1,%2,%3};"
                 : "+f"(d[0]), "+f"(d[1]), "+f"(d[2]), "+f"(d[3])
                 : "r"(a[0]), "r"(a[1]), "r"(a[2]), "r"(a[3]), "r"(b[0]), "r"(b[1]));
}
__device__ __forceinline__ void cpa16(uint32_t saddr, const void* g) {
    asm volatile("cp.async.ca.shared.global [%0], [%1], 16;" :: "r"(saddr), "l"(g));
}
#define CP_COMMIT() asm volatile("cp.async.commit_group;" ::: "memory")

#define PITCH 80   // bytes per smem row (32 fp16 data + pad); ldmatrix conflict-free

// ================= pipelined HMMA GEMM body ==================================
// C[BM x BN] = alpha*(A@B) (+bias)(+res)(+relu).
// A: fp16 hi only. B: fp16 hi+lo. K-major, BK=32, 2-stage cp.async.
// 2 MMAs per k16: A*B_hi + A*B_lo.
template<int BM, int BN, int NWARP, int HASBIAS, int RES, int RELU, int WF32, int WHI>
__device__ __forceinline__ void mma_body(
    const hf* __restrict__ A, int lda,
    const hf* __restrict__ Bh, const hf* __restrict__ Bl, int ldb,
    const float* __restrict__ bias, const float* __restrict__ Dres,
    float* __restrict__ C, hf* __restrict__ Ch, hf* __restrict__ Cl,
    int ldc, int K, float alpha)
{
    extern __shared__ __align__(128) char sm[];
    constexpr int THREADS = NWARP * 32;
    constexpr int ASZ = BM * PITCH;
    constexpr int BSZ = BN * PITCH;
    constexpr int STAGE = ASZ + 2 * BSZ;

    const int tid = threadIdx.x, lane = tid & 31, wid = tid >> 5;
    constexpr int WN  = 2;
    constexpr int WM  = NWARP / 2;
    constexpr int WTM = BM / WM;
    constexpr int WTN = BN / WN;
    constexpr int MI  = WTM / 16;
    constexpr int NI  = WTN / 8;
    const int wm = wid >> 1, wn = wid & 1;
    const uint32_t sb = smem_u32(sm);

    float acc[MI][NI][4];
#pragma unroll
    for (int i = 0; i < MI; i++)
#pragma unroll
        for (int j = 0; j < NI; j++)
#pragma unroll
            for (int r = 0; r < 4; r++) acc[i][j][r] = 0.f;

    const int NC = K >> 5;

    auto issue = [&](int st, int c) {
        const uint32_t base = sb + st * STAGE;
#pragma unroll
        for (int it = 0; it < BM * 4 / THREADS; it++) {     // A hi: BM rows x4 seg
            int idx = it * THREADS + tid;
            int r = idx >> 2, sg = idx & 3;
            const hf* g = A + (size_t)r * lda + (size_t)c * 32 + sg * 8;
            cpa16(base + r * PITCH + sg * 16, g);
        }
#pragma unroll
        for (int it = 0; it < BN * 8 / THREADS; it++) {     // B hi+lo
            int idx = it * THREADS + tid;
            int arr = idx / (BN * 4);
            int rem = idx % (BN * 4);
            int r = rem >> 2, sg = rem & 3;
            const hf* g = (arr ? Bl : Bh) + (size_t)r * ldb + (size_t)c * 32 + sg * 8;
            cpa16(base + ASZ + arr * BSZ + r * PITCH + sg * 16, g);
        }
    };

    issue(0, 0);
    CP_COMMIT();

    for (int c = 0; c < NC; c++) {
        const int st = c & 1;
        const bool pf = (c + 1 < NC);
        if (pf) { issue(st ^ 1, c + 1); CP_COMMIT(); }
        if (pf) { asm volatile("cp.async.wait_group 1;" ::: "memory"); }
        else    { asm volatile("cp.async.wait_group 0;" ::: "memory"); }
        __syncthreads();

        const uint32_t aH = sb + st * STAGE;
        const uint32_t bH = aH + ASZ;

#pragma unroll
        for (int ks = 0; ks < 2; ks++) {
            uint32_t Af[MI][4], Bf[NI][4];
            const int acol2 = (ks * 16 + ((lane >> 4) << 3)) * 2;
            // B merged hi/lo x4: lanes 0-7 hi@k0, 8-15 hi@k8, 16-23 lo@k0, 24-31 lo@k8
            const int bcol2 = (ks * 16 + (((lane >> 3) & 1) << 3)) * 2;
            const uint32_t bsel = (uint32_t)(lane >> 4) * BSZ;
#pragma unroll
            for (int ni = 0; ni < NI; ni++) {
                uint32_t o = (uint32_t)((wn * WTN + ni * 8 + (lane & 7)) * PITCH + bcol2) + bsel;
                ldsm_x4(Bf[ni][0], Bf[ni][1], Bf[ni][2], Bf[ni][3], bH + o);
            }
#pragma unroll
            for (int mi = 0; mi < MI; mi++) {
                uint32_t o = (uint32_t)((wm * WTM + mi * 16 + (lane & 15)) * PITCH + acol2);
                ldsm_x4(Af[mi][0], Af[mi][1], Af[mi][2], Af[mi][3], aH + o);
            }
#pragma unroll
            for (int mi = 0; mi < MI; mi++)
#pragma unroll
                for (int ni = 0; ni < NI; ni++) {
                    mma16816(acc[mi][ni], Af[mi], &Bf[ni][0]);   // A * B_hi
                    mma16816(acc[mi][ni], Af[mi], &Bf[ni][2]);   // A * B_lo
                }
        }
        __syncthreads();
    }

    // ---- epilogue ----
    const int groupID = lane >> 2, tig = lane & 3;
#pragma unroll
    for (int mi = 0; mi < MI; mi++) {
        const int r0 = wm * WTM + mi * 16 + groupID;
        const int r1 = r0 + 8;
#pragma unroll
        for (int ni = 0; ni < NI; ni++) {
            const int col = wn * WTN + ni * 8 + tig * 2;
            float2 v0, v1;
            v0.x = acc[mi][ni][0] * alpha; v0.y = acc[mi][ni][1] * alpha;
            v1.x = acc[mi][ni][2] * alpha; v1.y = acc[mi][ni][3] * alpha;
            if (HASBIAS) {
                v0.x += bias[col]; v0.y += bias[col + 1];
                v1.x += bias[col]; v1.y += bias[col + 1];
            }
            if (RES) {
                v0.x += Dres[(size_t)r0 * ldc + col];
                v0.y += Dres[(size_t)r0 * ldc + col + 1];
                v1.x += Dres[(size_t)r1 * ldc + col];
                v1.y += Dres[(size_t)r1 * ldc + col + 1];
            }
            if (RELU) {
                v0.x = fmaxf(v0.x, 0.f); v0.y = fmaxf(v0.y, 0.f);
                v1.x = fmaxf(v1.x, 0.f); v1.y = fmaxf(v1.y, 0.f);
            }
            if (WF32) {
                *(float2*)(C + (size_t)r0 * ldc + col) = v0;
                *(float2*)(C + (size_t)r1 * ldc + col) = v1;
            }
            if (WHI) {
                if (Cl) {          // hi + lo (B-side consumers)
                    uint32_t hi, lo;
                    split2h(v0.x, v0.y, hi, lo);
                    *(uint32_t*)(Ch + (size_t)r0 * ldc + col) = hi;
                    *(uint32_t*)(Cl + (size_t)r0 * ldc + col) = lo;
                    split2h(v1.x, v1.y, hi, lo);
                    *(uint32_t*)(Ch + (size_t)r1 * ldc + col) = hi;
                    *(uint32_t*)(Cl + (size_t)r1 * ldc + col) = lo;
                } else {           // hi only (A-side consumers)
                    *(uint32_t*)(Ch + (size_t)r0 * ldc + col) = pack_hi2(v0.x, v0.y);
                    *(uint32_t*)(Ch + (size_t)r1 * ldc + col) = pack_hi2(v1.x, v1.y);
                }
            }
        }
    }
}

// ================= GEMM kernels ==============================================
template<int RES, int RELU, int WF32, int WHI>
__global__ void __launch_bounds__(128, 2) mm_dense_kernel(
    const hf* __restrict__ A,
    const hf* __restrict__ Bh, const hf* __restrict__ Bl,
    const float* __restrict__ bias, const float* __restrict__ Dres,
    float* __restrict__ C, hf* __restrict__ Ch, hf* __restrict__ Cl,
    int N, int K)
{
    const int bm = blockIdx.y * 128, bn = blockIdx.x * 128;
    mma_body<128, 128, 4, 1, RES, RELU, WF32, WHI>(
        A + (size_t)bm * K, K,
        Bh + (size_t)bn * K, Bl + (size_t)bn * K, K,
        bias + bn,
        RES ? (Dres + (size_t)bm * N + bn) : (const float*)0,
        WF32 ? (C + (size_t)bm * N + bn) : (float*)0,
        WHI ? (Ch + (size_t)bm * N + bn) : (hf*)0,
        (WHI && Cl) ? (Cl + (size_t)bm * N + bn) : (hf*)0,
        N, K, 1.0f);
}

__global__ void __launch_bounds__(128, 2) mm_qkv_kernel(
    const hf* __restrict__ Hm,
    const hf* __restrict__ WQh, const hf* __restrict__ WQl, const float* __restrict__ bq,
    hf* __restrict__ Qh,
    const hf* __restrict__ WKh, const hf* __restrict__ WKl, const float* __restrict__ bk,
    hf* __restrict__ Kh, hf* __restrict__ Kl,
    const hf* __restrict__ WVh, const hf* __restrict__ WVl, const float* __restrict__ bv,
    hf* __restrict__ Vh, hf* __restrict__ Vl)
{
    const hf *Wh, *Wl; const float* b; hf *Oh; hf *Ol;
    if (blockIdx.z == 0)      { Wh = WQh; Wl = WQl; b = bq; Oh = Qh; Ol = (hf*)0; }
    else if (blockIdx.z == 1) { Wh = WKh; Wl = WKl; b = bk; Oh = Kh; Ol = Kl; }
    else                      { Wh = WVh; Wl = WVl; b = bv; Oh = Vh; Ol = Vl; }
    const int bm = blockIdx.y * 128, bn = blockIdx.x * 128;
    mma_body<128, 128, 4, 1, 0, 0, 0, 1>(
        Hm + (size_t)bm * DM, DM,
        Wh + (size_t)bn * DM, Wl + (size_t)bn * DM, DM,
        b + bn, (const float*)0,
        (float*)0,
        Oh + (size_t)bm * DM + bn,
        Ol ? (Ol + (size_t)bm * DM + bn) : (hf*)0,
        DM, DM, 1.0f);
}

__global__ void __launch_bounds__(128, 2) mm_scores_kernel(
    const hf* __restrict__ Q,
    const hf* __restrict__ Kh, const hf* __restrict__ Kl,
    float* __restrict__ P)
{
    const int kt = blockIdx.x, qt = blockIdx.y, h = blockIdx.z;
    if (kt > qt) return;
    mma_body<128, 128, 4, 0, 0, 0, 1, 0>(
        Q + (size_t)(qt * 128) * DM + h * DK, DM,
        Kh + (size_t)(kt * 128) * DM + h * DK, Kl + (size_t)(kt * 128) * DM + h * DK, DM,
        (const float*)0, (const float*)0,
        P + (size_t)h * S * S + (size_t)(qt * 128) * S + kt * 128,
        (hf*)0, (hf*)0, S, DK, 0.125f);
}

__global__ void __launch_bounds__(256, 2) mm_ctx_kernel(
    const hf* __restrict__ Pp,
    const hf* __restrict__ Vth, const hf* __restrict__ Vtl,
    hf* __restrict__ Ch)
{
    const int qt = blockIdx.x, h = blockIdx.y;
    mma_body<128, 64, 8, 0, 0, 0, 0, 1>(
        Pp + (size_t)h * S * S + (size_t)(qt * 128) * S, S,
        Vth + (size_t)h * DK * S, Vtl + (size_t)h * DK * S, S,
        (const float*)0, (const float*)0,
        (float*)0,
        Ch + (size_t)(qt * 128) * DM + h * DK, (hf*)0,
        DM, (qt + 1) * 128, 1.0f);
}

// ================= fused weight prep =========================================
__global__ void __launch_bounds__(256) prep_all_kernel(
    const float* __restrict__ W_in, hf* __restrict__ wInh, hf* __restrict__ wInl,
    const float* __restrict__ Wq,  hf* __restrict__ wQh,  hf* __restrict__ wQl,
    const float* __restrict__ Wk,  hf* __restrict__ wKh,  hf* __restrict__ wKl,
    const float* __restrict__ Wv,  hf* __restrict__ wVh,  hf* __restrict__ wVl,
    const float* __restrict__ Wo,  hf* __restrict__ wOh,  hf* __restrict__ wOl,
    const float* __restrict__ W2,  hf* __restrict__ w2h,  hf* __restrict__ w2l,
    const float* __restrict__ Wf1, hf* __restrict__ wF1h, hf* __restrict__ wF1l,
    const float* __restrict__ Wf2, hf* __restrict__ wF2h, hf* __restrict__ wF2l)
{
    const int b = blockIdx.x;
    const float* W; hf* Bh; hf* Bl; int N, K, t;
    if (b < 6144) {
        const int wi = b >> 10;
        t = b & 1023;
        N = DM; K = DM;
        switch (wi) {
            case 0: W = W_in; Bh = wInh; Bl = wInl; break;
            case 1: W = Wq;   Bh = wQh;  Bl = wQl;  break;
            case 2: W = Wk;   Bh = wKh;  Bl = wKl;  break;
            case 3: W = Wv;   Bh = wVh;  Bl = wVl;  break;
            case 4: W = Wo;   Bh = wOh;  Bl = wOl;  break;
            default: W = W2;  Bh = w2h;  Bl = w2l;  break;
        }
    } else if (b < 10240) {
        t = b - 6144; N = DFF; K = DM;  W = Wf1; Bh = wF1h; Bl = wF1l;
    } else {
        t = b - 10240; N = DM; K = DFF; W = Wf2; Bh = wF2h; Bl = wF2l;
    }
    const int nx = N / 32;
    const int n0 = (t % nx) * 32, k0 = (t / nx) * 32;

    __shared__ float tt[32][33];
    const int tx = threadIdx.x & 31, ty = threadIdx.x >> 5;
#pragma unroll
    for (int i = 0; i < 4; i++) {
        int k = ty + i * 8;
        tt[k][tx] = W[(size_t)(k0 + k) * N + n0 + tx];
    }
    __syncthreads();
#pragma unroll
    for (int i = 0; i < 4; i++) {
        int n = ty + i * 8;
        hf h, l;
        split1h(tt[tx][n], h, l);
        size_t o = (size_t)(n0 + n) * K + k0 + tx;
        Bh[o] = h;
        Bl[o] = l;
    }
}

// vt[h][c][s] = v[s][h*64+c] (hi & lo)
__global__ void __launch_bounds__(256) prep_vt_kernel(
    const hf* __restrict__ Vh, const hf* __restrict__ Vl,
    hf* __restrict__ Vth, hf* __restrict__ Vtl)
{
    __shared__ hf th[32][33], tl[32][33];
    const int s0 = blockIdx.x * 32, c0 = blockIdx.y * 32, h = blockIdx.z;
    const int tx = threadIdx.x & 31, ty = threadIdx.x >> 5;
#pragma unroll
    for (int i = 0; i < 4; i++) {
        int s = ty + i * 8;
        th[s][tx] = Vh[(size_t)(s0 + s) * DM + h * DK + c0 + tx];
        tl[s][tx] = Vl[(size_t)(s0 + s) * DM + h * DK + c0 + tx];
    }
    __syncthreads();
#pragma unroll
    for (int i = 0; i < 4; i++) {
        int cc = ty + i * 8;
        size_t o = ((size_t)h * DK + c0 + cc) * S + s0 + tx;
        Vth[o] = th[tx][cc];
        Vtl[o] = tl[tx][cc];
    }
}

// ================= LN / softmax ==============================================
__device__ __forceinline__ float warp_sum(float v) {
#pragma unroll
    for (int o = 16; o > 0; o >>= 1) v += __shfl_xor_sync(0xffffffffu, v, o);
    return v;
}
__device__ __forceinline__ float warp_max(float v) {
#pragma unroll
    for (int o = 16; o > 0; o >>= 1) v = fmaxf(v, __shfl_xor_sync(0xffffffffu, v, o));
    return v;
}
__device__ __forceinline__ float block_sum(float v, float* red) {
    const int tid = threadIdx.x;
    v = warp_sum(v);
    if ((tid & 31) == 0) red[tid >> 5] = v;
    __syncthreads();
    float r = (tid < 8) ? red[tid] : 0.f;
    r = warp_sum(r);
    if (tid == 0) red[0] = r;
    __syncthreads();
    return red[0];
}
__device__ __forceinline__ float block_max(float v, float* red) {
    const int tid = threadIdx.x;
    v = warp_max(v);
    if ((tid & 31) == 0) red[tid >> 5] = v;
    __syncthreads();
    float r = (tid < 8) ? red[tid] : -3.0e38f;
    r = warp_max(r);
    if (tid == 0) red[0] = r;
    __syncthreads();
    return red[0];
}

template<int WF32>
__global__ void __launch_bounds__(256) ln_kernel(
    const float* __restrict__ x, const float* __restrict__ g, const float* __restrict__ b,
    float* __restrict__ y, hf* __restrict__ yh)
{
    const int row = blockIdx.x;
    const float4* xr = (const float4*)(x + (size_t)row * DM);
    __shared__ float red[8];
    const int tid = threadIdx.x;

    float4 xv = xr[tid];
    float s = xv.x + xv.y + xv.z + xv.w;
    const float mean = block_sum(s, red) * (1.f / DM);
    __syncthreads();

    float dx = xv.x - mean, dy = xv.y - mean, dz = xv.z - mean, dw = xv.w - mean;
    float v = dx * dx + dy * dy + dz * dz + dw * dw;
    const float var = block_sum(v, red) * (1.f / DM);
    const float inv = 1.f / (sqrtf(var) + 1e-6f);

    float4 gv = ((const float4*)g)[tid];
    float4 bv = ((const float4*)b)[tid];
    float4 o;
    o.x = gv.x * (dx * inv) + bv.x;
    o.y = gv.y * (dy * inv) + bv.y;
    o.z = gv.z * (dz * inv) + bv.z;
    o.w = gv.w * (dw * inv) + bv.w;
    if (WF32) ((float4*)(y + (size_t)row * DM))[tid] = o;

    *(uint2*)(yh + (size_t)row * DM + tid * 4) =
        make_uint2(pack_hi2(o.x, o.y), pack_hi2(o.z, o.w));
}

__global__ void __launch_bounds__(256) softmax_kernel(
    float* __restrict__ P, hf* __restrict__ Ph)
{
    const int row = blockIdx.x;          // h*S + q
    const int qi = row & (S - 1);
    float* p = P + (size_t)row * S;
    hf* ph = Ph + (size_t)row * S;
    const int n = qi + 1;
    const int bnd = ((qi >> 7) + 1) << 7;    // ctx reads hi only up to tile boundary
    __shared__ float red[8];
    const int tid = threadIdx.x;

    float m = -3.0e38f;
    for (int j = tid; j < n; j += 256) m = fmaxf(m, p[j]);
    m = block_max(m, red);
    __syncthreads();

    float sum = 0.f;
    for (int j = tid; j < n; j += 256) { float e = expf(p[j] - m); p[j] = e; sum += e; }
    sum = block_sum(sum, red);
    const float inv = 1.f / sum;

    for (int j = tid; j < n; j += 256) {
        float val = p[j] * inv;
        p[j] = val;
        ph[j] = __float2half_rn(val);
    }
    const hf z = __ushort_as_half(0);
    for (int j = n + tid; j < bnd; j += 256) ph[j] = z;
    for (int j = n + tid; j < S; j += 256) p[j] = 0.f;   // fp32 zeros: full row (output)
}

// ================= host orchestration ========================================
#define GETP(var, sym) cudaGetSymbolAddress((void**)&var, sym)

extern "C" void kernel_launch(void* const* d_in, const int* in_sizes, int n_in,
                              void* d_out, int out_size)
{
    const float* x     = (const float*)d_in[0];
    const float* g1    = (const float*)d_in[1];
    const float* beta1 = (const float*)d_in[2];
    const float* W_in  = (const float*)d_in[3];
    const float* b_in  = (const float*)d_in[4];
    const float* Wq    = (const float*)d_in[5];
    const float* bq    = (const float*)d_in[6];
    const float* Wk    = (const float*)d_in[7];
    const float* bk    = (const float*)d_in[8];
    const float* Wv    = (const float*)d_in[9];
    const float* bv    = (const float*)d_in[10];
    const float* Wo    = (const float*)d_in[11];
    const float* bo    = (const float*)d_in[12];
    const float* W2    = (const float*)d_in[13];
    const float* b2    = (const float*)d_in[14];
    const float* g2    = (const float*)d_in[15];
    const float* beta2 = (const float*)d_in[16];
    const float* Wf1   = (const float*)d_in[17];
    const float* bf1   = (const float*)d_in[18];
    const float* Wf2   = (const float*)d_in[19];
    const float* bf2   = (const float*)d_in[20];

    float* out  = (float*)d_out;                       // [S, DM]
    float* attn = (float*)d_out + (size_t)S * DM;      // [NH, S, S]

    float *p_part1, *p_norm2;
    GETP(p_part1, g_part1); GETP(p_norm2, g_norm2);

    hf *n1h, *hh, *qh, *kh, *kl, *vh, *vl, *vth, *vtl;
    hf *ctxh, *mhah, *n2h, *f1h, *pph;
    GETP(n1h, g_n1h);
    GETP(hh, g_hvh);
    GETP(qh, g_qh);
    GETP(kh, g_kh);   GETP(kl, g_kl);
    GETP(vh, g_vh);   GETP(vl, g_vl);
    GETP(vth, g_vth); GETP(vtl, g_vtl);
    GETP(ctxh, g_ctxh);
    GETP(mhah, g_mhah);
    GETP(n2h, g_n2h);
    GETP(f1h, g_f1h);
    GETP(pph, g_ph);

    hf *wInh, *wInl, *wQh, *wQl, *wKh, *wKl, *wVh, *wVl, *wOh, *wOl, *w2h, *w2l;
    hf *wF1h, *wF1l, *wF2h, *wF2l;
    GETP(wInh, g_wInh); GETP(wInl, g_wInl);
    GETP(wQh, g_wQh);   GETP(wQl, g_wQl);
    GETP(wKh, g_wKh);   GETP(wKl, g_wKl);
    GETP(wVh, g_wVh);   GETP(wVl, g_wVl);
    GETP(wOh, g_wOh);   GETP(wOl, g_wOl);
    GETP(w2h, g_w2h);   GETP(w2l, g_w2l);
    GETP(wF1h, g_wF1h); GETP(wF1l, g_wF1l);
    GETP(wF2h, g_wF2h); GETP(wF2l, g_wF2l);

    // smem sizes: stage = A(hi) + B(hi+lo), 2 stages
    const int SM_D = 2 * (128 * PITCH + 2 * 128 * PITCH);   // 61440
    const int SM_C = 2 * (128 * PITCH + 2 * 64 * PITCH);    // 40960
    cudaFuncSetAttribute(mm_dense_kernel<0,0,0,1>, cudaFuncAttributeMaxDynamicSharedMemorySize, SM_D);
    cudaFuncSetAttribute(mm_dense_kernel<1,0,1,0>, cudaFuncAttributeMaxDynamicSharedMemorySize, SM_D);
    cudaFuncSetAttribute(mm_dense_kernel<0,1,0,1>, cudaFuncAttributeMaxDynamicSharedMemorySize, SM_D);
    cudaFuncSetAttribute(mm_qkv_kernel,    cudaFuncAttributeMaxDynamicSharedMemorySize, SM_D);
    cudaFuncSetAttribute(mm_scores_kernel, cudaFuncAttributeMaxDynamicSharedMemorySize, SM_D);
    cudaFuncSetAttribute(mm_ctx_kernel,    cudaFuncAttributeMaxDynamicSharedMemorySize, SM_C);

    // 0. all weight prep in one launch
    prep_all_kernel<<<14336, 256>>>(
        W_in, wInh, wInl, Wq, wQh, wQl, Wk, wKh, wKl, Wv, wVh, wVl,
        Wo, wOh, wOl, W2, w2h, w2l, Wf1, wF1h, wF1l, Wf2, wF2h, wF2l);

    // 1. LN1 -> hi only
    ln_kernel<0><<<S, 256>>>(x, g1, beta1, nullptr, n1h);

    // 2. h = norm1 @ W_in + b_in  (hi only)
    mm_dense_kernel<0,0,0,1><<<dim3(DM/128, S/128), 128, SM_D>>>(
        n1h, wInh, wInl, b_in, nullptr, nullptr, hh, nullptr, DM, DM);

    // 3. q/k/v  (q: hi; k,v: hi+lo)
    mm_qkv_kernel<<<dim3(DM/128, S/128, 3), 128, SM_D>>>(
        hh, wQh, wQl, bq, qh, wKh, wKl, bk, kh, kl, wVh, wVl, bv, vh, vl);

    // 3b. V transpose per head
    prep_vt_kernel<<<dim3(S/32, DK/32, NH), 256>>>(vh, vl, vth, vtl);

    // 4. scores -> attn fp32; 5. softmax -> attn fp32 + P hi
    mm_scores_kernel<<<dim3(S/128, S/128, NH), 128, SM_D>>>(qh, kh, kl, attn);
    softmax_kernel<<<NH * S, 256>>>(attn, pph);

    // 6. ctx = P @ V (hi only)
    mm_ctx_kernel<<<dim3(S/128, NH), 256, SM_C>>>(pph, vth, vtl, ctxh);

    // 7. mha = ctx @ Wo + bo (hi only)
    mm_dense_kernel<0,0,0,1><<<dim3(DM/128, S/128), 128, SM_D>>>(
        ctxh, wOh, wOl, bo, nullptr, nullptr, mhah, nullptr, DM, DM);

    // 8. part1 = x + mha @ W2 + b2 (fp32)
    mm_dense_kernel<1,0,1,0><<<dim3(DM/128, S/128), 128, SM_D>>>(
        mhah, w2h, w2l, b2, x, p_part1, nullptr, nullptr, DM, DM);

    // 9. LN2 -> fp32 + hi
    ln_kernel<1><<<S, 256>>>(p_part1, g2, beta2, p_norm2, n2h);

    // 10. ff1 = relu(norm2 @ Wf1 + bf1) (hi only)
    mm_dense_kernel<0,1,0,1><<<dim3(DFF/128, S/128), 128, SM_D>>>(
        n2h, wF1h, wF1l, bf1, nullptr, nullptr, f1h, nullptr, DFF, DM);

    // 11. out = norm2 + ff1 @ Wf2 + bf2 (fp32)
    mm_dense_kernel<1,0,1,0><<<dim3(DM/128, S/128), 128, SM_D>>>(
        f1h, wF2h, wF2l, bf2, p_norm2, out, nullptr, nullptr, DM, DFF);
}